// round 6
// baseline (speedup 1.0000x reference)
#include <cuda_runtime.h>
#include <mma.h>
#include <cstdint>
#include <cstddef>

using namespace nvcuda;

#define MAXN 50000
#define MAXE 400000
#define PAD_ROWS 128

// ---------------- persistent device scratch (padded for unguarded GEMM tail stores) ------------
__device__ float d_t0[((size_t)MAXN + PAD_ROWS) * 256];
__device__ float d_w0[((size_t)MAXN + PAD_ROWS) * 256];
__device__ float d_t1[((size_t)MAXN + PAD_ROWS) * 256];
__device__ float d_w1[((size_t)MAXN + PAD_ROWS) * 256];
__device__ float d_hs[4 * (size_t)MAXN * 256 + PAD_ROWS * 256];  // GAT H buffers / SAGE1 y buffers
__device__ float d_el[4 * (size_t)MAXN * 4];
__device__ float d_er[4 * (size_t)MAXN * 4];
__device__ float d_alv[4 * 64 * 4];
__device__ float d_arv[4 * 64 * 4];
__device__ float d_wsum[2 * 256 * 64];
__device__ float d_bsum[128];
__device__ int   d_cnt[4 * MAXN];
__device__ int   d_rpv[4 * (MAXN + 1)];
__device__ int   d_colv[4 * MAXE];

__device__ __forceinline__ float to_tf32(float x)
{
    return wmma::__float_to_tf32(x);
}

// ---------------- TF32 split tensor-core GEMM: C[M,N] = A[M,K] @ B[K,N] (+bias)(relu) ----------
// BM=128, BN in {64,128}, BK=16, 256 threads (8 warps as 4x2), wmma m16n16k8,
// hi/lo split (3 MMAs) for ~fp32 accuracy. Tail M-rows stored unguarded (padded C).
template<int BN, bool VEC>
__launch_bounds__(256, 2)
__global__ void gemm_tc_kernel(const float* __restrict__ A, const float* __restrict__ B,
                               float* __restrict__ C, const float* __restrict__ bias,
                               int M, int N, int K, int relu)
{
    constexpr int BM  = 128;
    constexpr int SKA = 20;             // As row stride (floats)
    constexpr int SKB = BN + 4;         // Bs row stride
    constexpr int MI  = 2;              // 16-row frags per warp (warp tile 32 rows)
    constexpr int NI  = BN / 32;        // 16-col frags per warp (warp tile BN/2 cols)
    constexpr int BNF4 = (16 * BN / 4) / 256;   // B float4 loads per thread (VEC): 1 or 2
    constexpr int BSCN = 16 * BN / 256;         // B scalar loads per thread: 4 or 8

    __shared__ float As[2][BM][SKA];
    __shared__ float Bs[2][16][SKB];
    __shared__ float Brep[16][BN];

    const int tid = threadIdx.x;
    const int wid = tid >> 5;
    const int wm = wid & 3, wn = wid >> 2;
    const int m0 = blockIdx.y * BM, n0 = blockIdx.x * BN;
    const int mw = wm * 32;
    const int nw = wn * (BN / 2);

    float4 ra4[2];  float ras[8];
    float4 rb4[BNF4 > 0 ? BNF4 : 1];  float rbs[BSCN];

    // ---- tile load helpers ----
    auto ldA = [&](int t) {
        int k0 = t * 16;
        if (VEC) {
#pragma unroll
            for (int i = 0; i < 2; i++) {
                int idx = tid + i * 256;
                int r = idx >> 2, c4 = idx & 3;
                int gm = m0 + r;
                ra4[i] = (gm < M) ? *(const float4*)&A[(size_t)gm * K + k0 + c4 * 4]
                                  : make_float4(0.f, 0.f, 0.f, 0.f);
            }
        } else {
#pragma unroll
            for (int i = 0; i < 8; i++) {
                int idx = tid + i * 256;
                int r = idx >> 4, c = idx & 15;
                int gm = m0 + r;
                ras[i] = (gm < M && k0 + c < K) ? A[(size_t)gm * K + k0 + c] : 0.f;
            }
        }
    };
    auto stA = [&](int st) {
        if (VEC) {
#pragma unroll
            for (int i = 0; i < 2; i++) {
                int idx = tid + i * 256;
                int r = idx >> 2, c4 = idx & 3;
                *(float4*)&As[st][r][c4 * 4] = ra4[i];
            }
        } else {
#pragma unroll
            for (int i = 0; i < 8; i++) {
                int idx = tid + i * 256;
                int r = idx >> 4, c = idx & 15;
                As[st][r][c] = ras[i];
            }
        }
    };
    auto ldB = [&](int t) {
        int k0 = t * 16;
        if (VEC) {
#pragma unroll
            for (int i = 0; i < BNF4; i++) {
                int idx = tid + i * 256;
                int r = idx / (BN / 4), c4 = idx % (BN / 4);
                rb4[i] = *(const float4*)&B[(size_t)(k0 + r) * N + n0 + c4 * 4];
            }
        } else {
#pragma unroll
            for (int i = 0; i < BSCN; i++) {
                int idx = tid + i * 256;
                int r = idx / BN, c = idx % BN;
                rbs[i] = (k0 + r < K) ? B[(size_t)(k0 + r) * N + n0 + c] : 0.f;
            }
        }
    };
    auto stB = [&](int st) {
        if (VEC) {
#pragma unroll
            for (int i = 0; i < BNF4; i++) {
                int idx = tid + i * 256;
                int r = idx / (BN / 4), c4 = idx % (BN / 4);
                *(float4*)&Bs[st][r][c4 * 4] = rb4[i];
            }
        } else {
#pragma unroll
            for (int i = 0; i < BSCN; i++) {
                int idx = tid + i * 256;
                int r = idx / BN, c = idx % BN;
                Bs[st][r][c] = rbs[i];
            }
        }
    };

    // ---- prologue: stage k-tile 0, fill bias replication ----
    ldA(0); ldB(0);
    stA(0); stB(0);
    if (bias) {
        for (int i = tid; i < 16 * BN; i += 256)
            Brep[i / BN][i % BN] = bias[n0 + (i % BN)];
    }
    __syncthreads();

    wmma::fragment<wmma::accumulator, 16, 16, 8, float> cfr[MI][NI];
#pragma unroll
    for (int mi = 0; mi < MI; mi++)
#pragma unroll
        for (int ni = 0; ni < NI; ni++) {
            if (bias)
                wmma::load_matrix_sync(cfr[mi][ni], &Brep[0][nw + ni * 16], BN, wmma::mem_row_major);
            else
                wmma::fill_fragment(cfr[mi][ni], 0.f);
        }

    const int numK = (K + 15) >> 4;
    int cur = 0;
    for (int t = 0; t < numK; t++) {
        bool hasNext = (t + 1 < numK);
        if (hasNext) { ldA(t + 1); ldB(t + 1); }

        // ---- compute on stage cur: 2 k8-steps, hi/lo split, 3 MMAs per frag pair ----
#pragma unroll
        for (int ks = 0; ks < 16; ks += 8) {
            wmma::fragment<wmma::matrix_a, 16, 16, 8, wmma::precision::tf32, wmma::row_major> ah[MI], al[MI];
#pragma unroll
            for (int mi = 0; mi < MI; mi++) {
                wmma::fragment<wmma::matrix_a, 16, 16, 8, wmma::precision::tf32, wmma::row_major> ar;
                wmma::load_matrix_sync(ar, &As[cur][mw + mi * 16][ks], SKA);
#pragma unroll
                for (int q = 0; q < ar.num_elements; q++) {
                    float v = ar.x[q];
                    float h = to_tf32(v);
                    ah[mi].x[q] = h;
                    al[mi].x[q] = to_tf32(v - h);
                }
            }
#pragma unroll
            for (int ni = 0; ni < NI; ni++) {
                wmma::fragment<wmma::matrix_b, 16, 16, 8, wmma::precision::tf32, wmma::row_major> br, bh, bl;
                wmma::load_matrix_sync(br, &Bs[cur][ks][nw + ni * 16], SKB);
#pragma unroll
                for (int q = 0; q < br.num_elements; q++) {
                    float v = br.x[q];
                    float h = to_tf32(v);
                    bh.x[q] = h;
                    bl.x[q] = to_tf32(v - h);
                }
#pragma unroll
                for (int mi = 0; mi < MI; mi++) {
                    wmma::mma_sync(cfr[mi][ni], ah[mi], bh, cfr[mi][ni]);
                    wmma::mma_sync(cfr[mi][ni], al[mi], bh, cfr[mi][ni]);
                    wmma::mma_sync(cfr[mi][ni], ah[mi], bl, cfr[mi][ni]);
                }
            }
        }

        if (hasNext) {
            stA(cur ^ 1); stB(cur ^ 1);
            __syncthreads();
            cur ^= 1;
        }
    }

    // ---- epilogue: relu elementwise (layout-agnostic), direct store (C is padded) ----
#pragma unroll
    for (int mi = 0; mi < MI; mi++) {
        int gm = m0 + mw + mi * 16;
#pragma unroll
        for (int ni = 0; ni < NI; ni++) {
            if (relu) {
#pragma unroll
                for (int q = 0; q < cfr[mi][ni].num_elements; q++)
                    cfr[mi][ni].x[q] = fmaxf(cfr[mi][ni].x[q], 0.f);
            }
            wmma::store_matrix_sync(&C[(size_t)gm * N + n0 + nw + ni * 16], cfr[mi][ni], N,
                                    wmma::mem_row_major);
        }
    }
}

// ------------- fold attention vectors into K-side: v[k,h] = sum_d W[k, h*64+d]*a[h,d] --------
__global__ void attnvec_kernel(const float* __restrict__ W, const float* __restrict__ al,
                               const float* __restrict__ ar,
                               float* __restrict__ alv, float* __restrict__ arv)
{
    int idx = blockIdx.x * 256 + threadIdx.x;      // 2048 total
    if (idx >= 2048) return;
    int type = idx >> 10;
    int rem = idx & 1023;
    int r = rem >> 8;
    int k = (rem >> 2) & 63;
    int h = rem & 3;
    const float* av = type ? ar : al;
    float s = 0.f;
#pragma unroll 16
    for (int d = 0; d < 64; d++)
        s += W[(size_t)r * 16384 + (size_t)k * 256 + h * 64 + d] * av[r * 256 + h * 64 + d];
    (type ? arv : alv)[r * 256 + k * 4 + h] = s;
}

// ------------- fused el/er projection: one X read computes 4 vec-projections -------------
__global__ void vecproj_fused_kernel(const float* __restrict__ Xt, const float* __restrict__ Xw,
                                     const float* __restrict__ alv, const float* __restrict__ arv,
                                     float* __restrict__ el, float* __restrict__ er,
                                     int NT, int NW)
{
    int type = blockIdx.y;                 // 0 = tx nodes, 1 = w nodes
    const float* X = type ? Xw : Xt;
    int n = type ? NW : NT;
    int e0 = type ? 0 : 1;                 // el relations {e0, e0+2} (this type is src)
    int r0 = type ? 1 : 0;                 // er relations {r0, r0+2} (this type is dst)

    __shared__ float sv[4][256];
    for (int i = threadIdx.x; i < 1024; i += blockDim.x) {
        int v = i >> 8, c = i & 255;
        const float* src = (v < 2) ? (alv + (e0 + 2 * (v & 1)) * 256)
                                   : (arv + (r0 + 2 * (v & 1)) * 256);
        sv[v][c] = src[c];
    }
    __syncthreads();
    int i = blockIdx.x * blockDim.x + threadIdx.x;
    if (i >= n) return;
    const float* x = X + (size_t)i * 64;
    float a[4][4] = {};
#pragma unroll 8
    for (int k = 0; k < 64; k++) {
        float xv = __ldg(&x[k]);
#pragma unroll
        for (int v = 0; v < 4; v++) {
            float4 s4 = *(const float4*)&sv[v][k * 4];
            a[v][0] += xv * s4.x; a[v][1] += xv * s4.y;
            a[v][2] += xv * s4.z; a[v][3] += xv * s4.w;
        }
    }
    *(float4*)&el[(size_t)(e0)     * MAXN * 4 + (size_t)i * 4] = make_float4(a[0][0], a[0][1], a[0][2], a[0][3]);
    *(float4*)&el[(size_t)(e0 + 2) * MAXN * 4 + (size_t)i * 4] = make_float4(a[1][0], a[1][1], a[1][2], a[1][3]);
    *(float4*)&er[(size_t)(r0)     * MAXN * 4 + (size_t)i * 4] = make_float4(a[2][0], a[2][1], a[2][2], a[2][3]);
    *(float4*)&er[(size_t)(r0 + 2) * MAXN * 4 + (size_t)i * 4] = make_float4(a[3][0], a[3][1], a[3][2], a[3][3]);
}

// ---------------- CSR build ----------------
__global__ void hist_kernel(const int* __restrict__ edges, int* __restrict__ cnt, int E, int n)
{
    for (int idx = blockIdx.x * blockDim.x + threadIdx.x; idx < 4 * E; idx += gridDim.x * blockDim.x) {
        int r = idx / E, i = idx - r * E;
        int dst = edges[(size_t)(2 * r + 1) * E + i];
        atomicAdd(&cnt[r * n + dst], 1);
    }
}

__global__ void scan_kernel(const int* __restrict__ cnt, int* __restrict__ rp, int n)
{
    int r = blockIdx.x;
    int t = threadIdx.x;                      // 1024 threads
    int C = (n + 1023) / 1024;
    __shared__ int sums[1024];
    int base = t * C;
    int loc = 0;
    for (int i = 0; i < C; i++) {
        int idx = base + i;
        if (idx < n) loc += cnt[r * n + idx];
    }
    sums[t] = loc;
    __syncthreads();
    for (int off = 1; off < 1024; off <<= 1) {
        int v = (t >= off) ? sums[t - off] : 0;
        __syncthreads();
        sums[t] += v;
        __syncthreads();
    }
    int run = (t == 0) ? 0 : sums[t - 1];
    for (int i = 0; i < C; i++) {
        int idx = base + i;
        if (idx < n) {
            rp[(size_t)r * (n + 1) + idx] = run;
            run += cnt[r * n + idx];
        }
    }
    if (t == 1023) rp[(size_t)r * (n + 1) + n] = sums[1023];
}

__global__ void scatter_kernel(const int* __restrict__ edges, int* __restrict__ cnt,
                               const int* __restrict__ rp, int* __restrict__ col, int E, int n)
{
    for (int idx = blockIdx.x * blockDim.x + threadIdx.x; idx < 4 * E; idx += gridDim.x * blockDim.x) {
        int r = idx / E, i = idx - r * E;
        int src = edges[(size_t)(2 * r) * E + i];
        int dst = edges[(size_t)(2 * r + 1) * E + i];
        int pos = rp[(size_t)r * (n + 1) + dst] + atomicAdd(&cnt[r * n + dst], 1);
        col[(size_t)r * E + pos] = src;
    }
}

// ---------------- GAT aggregation: warp per dst, both node types, two relations fused --------
__device__ __forceinline__ float lrelu(float x) { return x > 0.f ? x : 0.2f * x; }

__global__ void gat_agg_kernel(float* __restrict__ Ot, float* __restrict__ Ow,
                               const float* __restrict__ hs,
                               const float* __restrict__ el, const float* __restrict__ er,
                               const int* __restrict__ rp, const int* __restrict__ col,
                               const float* __restrict__ gb, int NT, int NW, int E)
{
    const size_t HOF = (size_t)MAXN * 256;
    const size_t EO4 = (size_t)MAXN * 4;
    int yt = blockIdx.y;                 // 0 = tx dst (rel 0,2), 1 = w dst (rel 1,3)
    int n = yt ? NW : NT;
    float* out = yt ? Ow : Ot;
    int ra = yt, rb = yt + 2;

    int w = (blockIdx.x * blockDim.x + threadIdx.x) >> 5;
    int lane = threadIdx.x & 31;
    if (w >= n) return;

    float4 acc0 = make_float4(0.f, 0.f, 0.f, 0.f);
    float4 acc1 = make_float4(0.f, 0.f, 0.f, 0.f);

#pragma unroll
    for (int q = 0; q < 2; q++) {
        int rel = q ? rb : ra;
        const float* H   = hs + (size_t)rel * HOF;
        const float* elr = el + (size_t)rel * EO4;
        const float* err = er + (size_t)rel * EO4;
        const int* rpr   = rp + (size_t)rel * (MAXN + 1);
        const int* colr  = col + (size_t)rel * E;

        int s0 = rpr[w], s1 = rpr[w + 1];
        if (s1 <= s0) continue;

        float4 e4 = *(const float4*)(err + (size_t)w * 4);
        float er0 = e4.x, er1 = e4.y, er2 = e4.z, er3 = e4.w;

        float m0 = -1e30f, m1 = -1e30f, m2 = -1e30f, m3 = -1e30f;
        for (int e = s0 + lane; e < s1; e += 32) {
            int s = colr[e];
            float4 l4 = *(const float4*)(elr + (size_t)s * 4);
            m0 = fmaxf(m0, lrelu(l4.x + er0));
            m1 = fmaxf(m1, lrelu(l4.y + er1));
            m2 = fmaxf(m2, lrelu(l4.z + er2));
            m3 = fmaxf(m3, lrelu(l4.w + er3));
        }
#pragma unroll
        for (int o = 16; o; o >>= 1) {
            m0 = fmaxf(m0, __shfl_xor_sync(0xffffffffu, m0, o));
            m1 = fmaxf(m1, __shfl_xor_sync(0xffffffffu, m1, o));
            m2 = fmaxf(m2, __shfl_xor_sync(0xffffffffu, m2, o));
            m3 = fmaxf(m3, __shfl_xor_sync(0xffffffffu, m3, o));
        }
        float z0 = 0, z1 = 0, z2 = 0, z3 = 0;
        for (int e = s0 + lane; e < s1; e += 32) {
            int s = colr[e];
            float4 l4 = *(const float4*)(elr + (size_t)s * 4);
            z0 += __expf(lrelu(l4.x + er0) - m0);
            z1 += __expf(lrelu(l4.y + er1) - m1);
            z2 += __expf(lrelu(l4.z + er2) - m2);
            z3 += __expf(lrelu(l4.w + er3) - m3);
        }
#pragma unroll
        for (int o = 16; o; o >>= 1) {
            z0 += __shfl_xor_sync(0xffffffffu, z0, o);
            z1 += __shfl_xor_sync(0xffffffffu, z1, o);
            z2 += __shfl_xor_sync(0xffffffffu, z2, o);
            z3 += __shfl_xor_sync(0xffffffffu, z3, o);
        }
        float i0 = 1.f / z0, i1 = 1.f / z1, i2 = 1.f / z2, i3 = 1.f / z3;

        for (int e = s0; e < s1; e++) {
            int s = colr[e];
            float4 l4 = *(const float4*)(elr + (size_t)s * 4);
            float a0 = __expf(lrelu(l4.x + er0) - m0) * i0;
            float a1 = __expf(lrelu(l4.y + er1) - m1) * i1;
            float a2 = __expf(lrelu(l4.z + er2) - m2) * i2;
            float a3 = __expf(lrelu(l4.w + er3) - m3) * i3;
            float wA = (lane < 16) ? a0 : a1;
            float wB = (lane < 16) ? a2 : a3;
            const float4* hp = (const float4*)(H + (size_t)s * 256);
            float4 h0 = hp[lane];
            float4 h1 = hp[lane + 32];
            acc0.x = fmaf(wA, h0.x, acc0.x); acc0.y = fmaf(wA, h0.y, acc0.y);
            acc0.z = fmaf(wA, h0.z, acc0.z); acc0.w = fmaf(wA, h0.w, acc0.w);
            acc1.x = fmaf(wB, h1.x, acc1.x); acc1.y = fmaf(wB, h1.y, acc1.y);
            acc1.z = fmaf(wB, h1.z, acc1.z); acc1.w = fmaf(wB, h1.w, acc1.w);
        }
    }

    const float4* ba4 = (const float4*)(gb + (size_t)ra * 256);
    const float4* bb4 = (const float4*)(gb + (size_t)rb * 256);
    float4* op = (float4*)(out + (size_t)w * 256);
    {
        float4 x = ba4[lane], y = bb4[lane];
        float4 o;
        o.x = fmaxf(0.f, 0.5f * acc0.x + 0.5f * (x.x + y.x));
        o.y = fmaxf(0.f, 0.5f * acc0.y + 0.5f * (x.y + y.y));
        o.z = fmaxf(0.f, 0.5f * acc0.z + 0.5f * (x.z + y.z));
        o.w = fmaxf(0.f, 0.5f * acc0.w + 0.5f * (x.w + y.w));
        op[lane] = o;
    }
    {
        float4 x = ba4[lane + 32], y = bb4[lane + 32];
        float4 o;
        o.x = fmaxf(0.f, 0.5f * acc1.x + 0.5f * (x.x + y.x));
        o.y = fmaxf(0.f, 0.5f * acc1.y + 0.5f * (x.y + y.y));
        o.z = fmaxf(0.f, 0.5f * acc1.z + 0.5f * (x.z + y.z));
        o.w = fmaxf(0.f, 0.5f * acc1.w + 0.5f * (x.w + y.w));
        op[lane + 32] = o;
    }
}

// ---------------- weight pre-add for SAGE1 self branch ----------------
__global__ void wsum_kernel(const float* __restrict__ Ws, const float* __restrict__ b,
                            float* __restrict__ wsum, float* __restrict__ bsum)
{
    int i = blockIdx.x * 256 + threadIdx.x;
    if (i < 16384) wsum[i] = Ws[i] + Ws[2 * 16384 + i];                 // rel 0 + 2
    else if (i < 32768) { int j = i - 16384; wsum[i] = Ws[16384 + j] + Ws[3 * 16384 + j]; }
    if (i < 64) bsum[i] = b[i] + b[2 * 64 + i];
    else if (i < 128) { int j = i - 64; bsum[i] = b[64 + j] + b[3 * 64 + j]; }
}

// ------------- SAGE1 combine: X = relu(X + mean_a(ya) + mean_b(yb)), rows 64-wide ---------
__global__ void sage1_combine_kernel(float* __restrict__ X,
    const float* __restrict__ ya, const float* __restrict__ yb,
    const int* __restrict__ rpa, const int* __restrict__ cola,
    const int* __restrict__ rpb, const int* __restrict__ colb, int n)
{
    int w = (blockIdx.x * blockDim.x + threadIdx.x) >> 5;
    int lane = threadIdx.x & 31;
    if (w >= n) return;
    float mx = 0.f, my = 0.f;
    {
        int s0 = rpa[w], s1 = rpa[w + 1];
        float sx = 0.f, sy = 0.f;
        for (int e = s0; e < s1; e++) {
            int s = cola[e];
            float2 v = *(const float2*)&ya[(size_t)s * 64 + lane * 2];
            sx += v.x; sy += v.y;
        }
        float inv = 1.f / fmaxf((float)(s1 - s0), 1.f);
        mx += sx * inv; my += sy * inv;
    }
    {
        int s0 = rpb[w], s1 = rpb[w + 1];
        float sx = 0.f, sy = 0.f;
        for (int e = s0; e < s1; e++) {
            int s = colb[e];
            float2 v = *(const float2*)&yb[(size_t)s * 64 + lane * 2];
            sx += v.x; sy += v.y;
        }
        float inv = 1.f / fmaxf((float)(s1 - s0), 1.f);
        mx += sx * inv; my += sy * inv;
    }
    float2* xp = (float2*)&X[(size_t)w * 64 + lane * 2];
    float2 xv = *xp;
    xv.x = fmaxf(xv.x + mx, 0.f);
    xv.y = fmaxf(xv.y + my, 0.f);
    *xp = xv;
}

// ------------- SAGE2 projections: self (Ws_a+Ws_b) and two y = X@Wn, all dim 2 -------------
__global__ void proj6_kernel(const float* __restrict__ X,
    const float* __restrict__ WsA, const float* __restrict__ WsB,
    const float* __restrict__ WnA, const float* __restrict__ WnB,
    float* __restrict__ selfO, float* __restrict__ yA, float* __restrict__ yB, int n)
{
    __shared__ float sw[3][512];
    for (int i = threadIdx.x; i < 512; i += blockDim.x) {
        sw[0][i] = WsA[i] + WsB[i];
        sw[1][i] = WnA[i];
        sw[2][i] = WnB[i];
    }
    __syncthreads();
    int w = (blockIdx.x * blockDim.x + threadIdx.x) >> 5;
    int lane = threadIdx.x & 31;
    if (w >= n) return;
    float a[6] = {0.f, 0.f, 0.f, 0.f, 0.f, 0.f};
    for (int k = lane; k < 256; k += 32) {
        float x = X[(size_t)w * 256 + k];
        a[0] += x * sw[0][2 * k]; a[1] += x * sw[0][2 * k + 1];
        a[2] += x * sw[1][2 * k]; a[3] += x * sw[1][2 * k + 1];
        a[4] += x * sw[2][2 * k]; a[5] += x * sw[2][2 * k + 1];
    }
#pragma unroll
    for (int o = 16; o; o >>= 1)
#pragma unroll
        for (int j = 0; j < 6; j++)
            a[j] += __shfl_xor_sync(0xffffffffu, a[j], o);
    if (lane == 0) {
        *(float2*)&selfO[(size_t)w * 2] = make_float2(a[0], a[1]);
        *(float2*)&yA[(size_t)w * 2]    = make_float2(a[2], a[3]);
        *(float2*)&yB[(size_t)w * 2]    = make_float2(a[4], a[5]);
    }
}

// ------------- SAGE2 combine: out = self + bA + bB + mean_a(yA) + mean_b(yB) -------------
__global__ void sage2_combine_kernel(float* __restrict__ out,
    const float* __restrict__ selfO, const float* __restrict__ yA, const float* __restrict__ yB,
    const int* __restrict__ rpa, const int* __restrict__ cola,
    const int* __restrict__ rpb, const int* __restrict__ colb,
    const float* __restrict__ bA, const float* __restrict__ bB, int n)
{
    int w = blockIdx.x * blockDim.x + threadIdx.x;
    if (w >= n) return;
    float2 r = *(const float2*)&selfO[(size_t)w * 2];
    r.x += bA[0] + bB[0];
    r.y += bA[1] + bB[1];
    {
        int s0 = rpa[w], s1 = rpa[w + 1];
        float sx = 0.f, sy = 0.f;
        for (int e = s0; e < s1; e++) {
            float2 v = *(const float2*)&yA[(size_t)cola[e] * 2];
            sx += v.x; sy += v.y;
        }
        float inv = 1.f / fmaxf((float)(s1 - s0), 1.f);
        r.x += sx * inv; r.y += sy * inv;
    }
    {
        int s0 = rpb[w], s1 = rpb[w + 1];
        float sx = 0.f, sy = 0.f;
        for (int e = s0; e < s1; e++) {
            float2 v = *(const float2*)&yB[(size_t)colb[e] * 2];
            sx += v.x; sy += v.y;
        }
        float inv = 1.f / fmaxf((float)(s1 - s0), 1.f);
        r.x += sx * inv; r.y += sy * inv;
    }
    *(float2*)&out[(size_t)w * 2] = r;
}

// ---------------- host helpers ----------------
static void gemm1(const float* A, const float* B, float* C, const float* bias,
                  int M, int N, int K, int relu)
{
    bool vec = ((K & 15) == 0);
    if (N % 128 == 0) {
        dim3 g(N / 128, (M + 127) / 128);
        if (vec) gemm_tc_kernel<128, true><<<g, 256>>>(A, B, C, bias, M, N, K, relu);
        else     gemm_tc_kernel<128, false><<<g, 256>>>(A, B, C, bias, M, N, K, relu);
    } else {
        dim3 g(N / 64, (M + 127) / 128);
        if (vec) gemm_tc_kernel<64, true><<<g, 256>>>(A, B, C, bias, M, N, K, relu);
        else     gemm_tc_kernel<64, false><<<g, 256>>>(A, B, C, bias, M, N, K, relu);
    }
}

static void gat_layer(const float* gW, const float* gal, const float* gar, const float* gb,
                      const float* Xt, const float* Xw, float* Ot, float* Ow,
                      float* hs, float* el, float* er, float* alv, float* arv,
                      const int* rp, const int* col, int NT, int NW, int E)
{
    const size_t HOF = (size_t)MAXN * 256;
    attnvec_kernel<<<8, 256>>>(gW, gal, gar, alv, arv);
    for (int r = 0; r < 4; r++) {
        const float* Xs = (r & 1) ? Xt : Xw;
        int Ns = (r & 1) ? NT : NW;
        gemm1(Xs, gW + (size_t)r * 64 * 256, hs + (size_t)r * HOF, nullptr, Ns, 256, 64, 0);
    }
    int nmax = NT > NW ? NT : NW;
    dim3 gv((nmax + 255) / 256, 2);
    vecproj_fused_kernel<<<gv, 256>>>(Xt, Xw, alv, arv, el, er, NT, NW);
    dim3 ga((nmax + 7) / 8, 2);
    gat_agg_kernel<<<ga, 256>>>(Ot, Ow, hs, el, er, rp, col, gb, NT, NW, E);
}

extern "C" void kernel_launch(void* const* d_in, const int* in_sizes, int n_in,
                              void* d_out, int out_size)
{
    const float* tx_feat  = (const float*)d_in[0];
    const float* w_feat   = (const float*)d_in[1];
    const int*   edges    = (const int*)d_in[2];
    const float* tx_W     = (const float*)d_in[3];
    const float* tx_b     = (const float*)d_in[4];
    const float* w_W      = (const float*)d_in[5];
    const float* w_b      = (const float*)d_in[6];
    const float* gat1_W   = (const float*)d_in[7];
    const float* gat1_al  = (const float*)d_in[8];
    const float* gat1_ar  = (const float*)d_in[9];
    const float* gat1_b   = (const float*)d_in[10];
    const float* sage1_Ws = (const float*)d_in[11];
    const float* sage1_Wn = (const float*)d_in[12];
    const float* sage1_b  = (const float*)d_in[13];
    const float* gat2_W   = (const float*)d_in[14];
    const float* gat2_al  = (const float*)d_in[15];
    const float* gat2_ar  = (const float*)d_in[16];
    const float* gat2_b   = (const float*)d_in[17];
    const float* sage2_Ws = (const float*)d_in[18];
    const float* sage2_Wn = (const float*)d_in[19];
    const float* sage2_b  = (const float*)d_in[20];

    int NT = in_sizes[0] / 166;
    int NW = in_sizes[1] / 56;
    int E  = in_sizes[2] / 8;
    if (NT > MAXN) NT = MAXN;
    if (NW > MAXN) NW = MAXN;
    if (E > MAXE) E = MAXE;

    float *t0, *w0, *t1, *w1, *hs, *el, *er, *alv, *arv, *wsum, *bsum;
    int *cnt, *rp, *col;
    cudaGetSymbolAddress((void**)&t0, d_t0);
    cudaGetSymbolAddress((void**)&w0, d_w0);
    cudaGetSymbolAddress((void**)&t1, d_t1);
    cudaGetSymbolAddress((void**)&w1, d_w1);
    cudaGetSymbolAddress((void**)&hs, d_hs);
    cudaGetSymbolAddress((void**)&el, d_el);
    cudaGetSymbolAddress((void**)&er, d_er);
    cudaGetSymbolAddress((void**)&alv, d_alv);
    cudaGetSymbolAddress((void**)&arv, d_arv);
    cudaGetSymbolAddress((void**)&wsum, d_wsum);
    cudaGetSymbolAddress((void**)&bsum, d_bsum);
    cudaGetSymbolAddress((void**)&cnt, d_cnt);
    cudaGetSymbolAddress((void**)&rp, d_rpv);
    cudaGetSymbolAddress((void**)&col, d_colv);

    float* fout = (float*)d_out;
    const size_t Y64 = (size_t)MAXN * 64;     // SAGE1 y buffer stride inside d_hs
    const int* rp0 = rp;  const int* rp1 = rp + (MAXN + 1);
    const int* rp2 = rp + 2 * (MAXN + 1);  const int* rp3 = rp + 3 * (MAXN + 1);
    const int* col0 = col; const int* col1 = col + (size_t)E;
    const int* col2 = col + 2 * (size_t)E; const int* col3 = col + 3 * (size_t)E;

    // ---- CSR build (per relation, dst-sorted) ----
    cudaMemsetAsync(cnt, 0, 4 * (size_t)MAXN * sizeof(int));
    hist_kernel<<<(4 * E + 255) / 256, 256>>>(edges, cnt, E, NT);
    scan_kernel<<<4, 1024>>>(cnt, rp, NT);
    cudaMemsetAsync(cnt, 0, 4 * (size_t)MAXN * sizeof(int));
    scatter_kernel<<<(4 * E + 255) / 256, 256>>>(edges, cnt, rp, col, E, NT);

    // ---- S0: input projections (relu) -> width 64 ----
    gemm1(tx_feat, tx_W, t0, tx_b, NT, 64, 166, 1);
    gemm1(w_feat,  w_W,  w0, w_b,  NW, 64, 56,  1);

    // ---- S1: hetero GAT1 (64 -> 256, relu fused) ----
    gat_layer(gat1_W, gat1_al, gat1_ar, gat1_b, t0, w0, t1, w1,
              hs, el, er, alv, arv, rp, col, NT, NW, E);

    // ---- S2: hetero SAGE1 (256 -> 64): project-then-aggregate ----
    {
        wsum_kernel<<<128, 256>>>(sage1_Ws, sage1_b, wsum, bsum);
        // self branches
        gemm1(t1, wsum,         t0, bsum,      NT, 64, 256, 0);
        gemm1(w1, wsum + 16384, w0, bsum + 64, NW, 64, 256, 0);
        // neighbor projections y_r = X_src @ Wn_r  (src of rel r: odd -> t, even -> w)
        gemm1(w1, sage1_Wn + 0 * 16384, hs + 0 * Y64, nullptr, NW, 64, 256, 0);
        gemm1(t1, sage1_Wn + 1 * 16384, hs + 1 * Y64, nullptr, NT, 64, 256, 0);
        gemm1(w1, sage1_Wn + 2 * 16384, hs + 2 * Y64, nullptr, NW, 64, 256, 0);
        gemm1(t1, sage1_Wn + 3 * 16384, hs + 3 * Y64, nullptr, NT, 64, 256, 0);
        // combine with segment means + relu (in place)
        sage1_combine_kernel<<<(NT + 7) / 8, 256>>>(t0, hs + 0 * Y64, hs + 2 * Y64,
                                                    rp0, col0, rp2, col2, NT);
        sage1_combine_kernel<<<(NW + 7) / 8, 256>>>(w0, hs + 1 * Y64, hs + 3 * Y64,
                                                    rp1, col1, rp3, col3, NW);
    }

    // ---- S3: hetero GAT2 (64 -> 256, relu fused) ----
    gat_layer(gat2_W, gat2_al, gat2_ar, gat2_b, t0, w0, t1, w1,
              hs, el, er, alv, arv, rp, col, NT, NW, E);

    // ---- S4: hetero SAGE2 (256 -> 2): project-then-aggregate ----
    {
        const size_t Y2 = (size_t)MAXN * 2;
        float* y0 = el + 0 * Y2;  float* y1 = el + 1 * Y2;
        float* y2 = el + 2 * Y2;  float* y3 = el + 3 * Y2;
        float* selfT = er + 0 * Y2;
        float* selfW = er + 1 * Y2;
        // t-nodes: self uses Ws0+Ws2; t is src of rel 1,3
        proj6_kernel<<<(NT + 7) / 8, 256>>>(t1, sage2_Ws + 0 * 512, sage2_Ws + 2 * 512,
                                            sage2_Wn + 1 * 512, sage2_Wn + 3 * 512,
                                            selfT, y1, y3, NT);
        // w-nodes: self uses Ws1+Ws3; w is src of rel 0,2
        proj6_kernel<<<(NW + 7) / 8, 256>>>(w1, sage2_Ws + 1 * 512, sage2_Ws + 3 * 512,
                                            sage2_Wn + 0 * 512, sage2_Wn + 2 * 512,
                                            selfW, y0, y2, NW);
        sage2_combine_kernel<<<(NT + 255) / 256, 256>>>(fout, selfT, y0, y2,
            rp0, col0, rp2, col2, sage2_b + 0, sage2_b + 4, NT);
        sage2_combine_kernel<<<(NW + 255) / 256, 256>>>(fout + (size_t)NT * 2, selfW, y1, y3,
            rp1, col1, rp3, col3, sage2_b + 2, sage2_b + 6, NW);
    }
}

// round 7
// speedup vs baseline: 1.0027x; 1.0027x over previous
#include <cuda_runtime.h>
#include <mma.h>
#include <cstdint>
#include <cstddef>

using namespace nvcuda;

#define MAXN 50000
#define MAXE 400000
#define PAD_ROWS 128

// ---------------- persistent device scratch (padded for unguarded GEMM tail stores) ------------
__device__ float d_t0[((size_t)MAXN + PAD_ROWS) * 256];
__device__ float d_w0[((size_t)MAXN + PAD_ROWS) * 256];
__device__ float d_t1[((size_t)MAXN + PAD_ROWS) * 256];
__device__ float d_w1[((size_t)MAXN + PAD_ROWS) * 256];
__device__ float d_hs[(size_t)MAXN * 1024 + PAD_ROWS * 512];  // packed H (2 x [MAXN,512]) / packed Y
__device__ float d_el[4 * (size_t)MAXN * 4];
__device__ float d_er[4 * (size_t)MAXN * 4];
__device__ float d_alv[4 * 64 * 4];
__device__ float d_arv[4 * 64 * 4];
__device__ float d_bh[65536];
__device__ float d_bl[65536];
__device__ float d_bsum[128];
__device__ int   d_cnt[4 * MAXN];
__device__ int   d_rpv[4 * (MAXN + 1)];
__device__ int   d_colv[4 * MAXE];

__device__ __forceinline__ float to_tf32(float x) { return wmma::__float_to_tf32(x); }

// ---------------- TF32 split tensor-core GEMM with pre-split B ----------------
// C[M,N] = A[M,K] @ B[K,N] (+bias)(relu), B given as hi/lo tf32 pair in global.
// BM=128, BN=64, BK=16, 256 threads (8 warps 4x2), wmma m16n16k8.
// 3-term split: Ah*Bh + Al*Bh + Ah*Bl (~fp32 accuracy). Tail rows stored unguarded (padded C).
template<bool VEC>
__launch_bounds__(256, 2)
__global__ void gemm_ts_kernel(const float* __restrict__ A,
                               const float* __restrict__ Bh, const float* __restrict__ Bl,
                               float* __restrict__ C, const float* __restrict__ bias,
                               int M, int N, int K, int relu)
{
    constexpr int BM = 128, BN = 64, SKA = 20, SKB = 68;
    __shared__ float As[2][BM][SKA];
    __shared__ float Bhs[2][16][SKB];
    __shared__ float Bls[2][16][SKB];
    __shared__ float Brep[16][BN];

    const int tid = threadIdx.x;
    const int wid = tid >> 5;
    const int wm = wid & 3, wn = wid >> 2;          // 4 x 2 warp grid
    const int m0 = blockIdx.y * BM, n0 = blockIdx.x * BN;
    const int mw = wm * 32;                          // warp tile: 32 rows x 32 cols
    const int nw = wn * 32;

    float4 ra4[2];  float ras[8];
    float4 rbh4;    float rbhs[4];
    float4 rbl4;    float rbls[4];

    auto ldA = [&](int t) {
        int k0 = t * 16;
        if (VEC) {
#pragma unroll
            for (int i = 0; i < 2; i++) {
                int idx = tid + i * 256;
                int r = idx >> 2, c4 = idx & 3;
                int gm = m0 + r;
                ra4[i] = (gm < M) ? *(const float4*)&A[(size_t)gm * K + k0 + c4 * 4]
                                  : make_float4(0.f, 0.f, 0.f, 0.f);
            }
        } else {
#pragma unroll
            for (int i = 0; i < 8; i++) {
                int idx = tid + i * 256;
                int r = idx >> 4, c = idx & 15;
                int gm = m0 + r;
                ras[i] = (gm < M && k0 + c < K) ? A[(size_t)gm * K + k0 + c] : 0.f;
            }
        }
    };
    auto stA = [&](int st) {
        if (VEC) {
#pragma unroll
            for (int i = 0; i < 2; i++) {
                int idx = tid + i * 256;
                int r = idx >> 2, c4 = idx & 3;
                *(float4*)&As[st][r][c4 * 4] = ra4[i];
            }
        } else {
#pragma unroll
            for (int i = 0; i < 8; i++) {
                int idx = tid + i * 256;
                int r = idx >> 4, c = idx & 15;
                As[st][r][c] = ras[i];
            }
        }
    };
    auto ldB = [&](int t) {
        int k0 = t * 16;
        if (VEC) {
            int r = tid >> 4, c4 = tid & 15;         // 16 rows x 64 cols = exactly 1 float4/thread
            rbh4 = *(const float4*)&Bh[(size_t)(k0 + r) * N + n0 + c4 * 4];
            rbl4 = *(const float4*)&Bl[(size_t)(k0 + r) * N + n0 + c4 * 4];
        } else {
#pragma unroll
            for (int i = 0; i < 4; i++) {
                int idx = tid + i * 256;
                int r = idx >> 6, c = idx & 63;
                bool ok = (k0 + r) < K;
                rbhs[i] = ok ? Bh[(size_t)(k0 + r) * N + n0 + c] : 0.f;
                rbls[i] = ok ? Bl[(size_t)(k0 + r) * N + n0 + c] : 0.f;
            }
        }
    };
    auto stB = [&](int st) {
        if (VEC) {
            int r = tid >> 4, c4 = tid & 15;
            *(float4*)&Bhs[st][r][c4 * 4] = rbh4;
            *(float4*)&Bls[st][r][c4 * 4] = rbl4;
        } else {
#pragma unroll
            for (int i = 0; i < 4; i++) {
                int idx = tid + i * 256;
                int r = idx >> 6, c = idx & 63;
                Bhs[st][r][c] = rbhs[i];
                Bls[st][r][c] = rbls[i];
            }
        }
    };

    // ---- prologue ----
    ldA(0); ldB(0);
    stA(0); stB(0);
    if (bias) {
        for (int i = tid; i < 16 * BN; i += 256)
            Brep[i >> 6][i & 63] = bias[n0 + (i & 63)];
    }
    __syncthreads();

    wmma::fragment<wmma::accumulator, 16, 16, 8, float> cfr[2][2];
#pragma unroll
    for (int mi = 0; mi < 2; mi++)
#pragma unroll
        for (int ni = 0; ni < 2; ni++) {
            if (bias)
                wmma::load_matrix_sync(cfr[mi][ni], &Brep[0][nw + ni * 16], BN, wmma::mem_row_major);
            else
                wmma::fill_fragment(cfr[mi][ni], 0.f);
        }

    const int numK = (K + 15) >> 4;
    int cur = 0;
    for (int t = 0; t < numK; t++) {
        bool hasNext = (t + 1 < numK);
        if (hasNext) { ldA(t + 1); ldB(t + 1); }

#pragma unroll
        for (int ks = 0; ks < 16; ks += 8) {
            wmma::fragment<wmma::matrix_a, 16, 16, 8, wmma::precision::tf32, wmma::row_major> ah[2], al[2];
#pragma unroll
            for (int mi = 0; mi < 2; mi++) {
                wmma::fragment<wmma::matrix_a, 16, 16, 8, wmma::precision::tf32, wmma::row_major> ar;
                wmma::load_matrix_sync(ar, &As[cur][mw + mi * 16][ks], SKA);
#pragma unroll
                for (int q = 0; q < ar.num_elements; q++) {
                    float v = ar.x[q];
                    float h = to_tf32(v);
                    ah[mi].x[q] = h;
                    al[mi].x[q] = to_tf32(v - h);
                }
            }
#pragma unroll
            for (int ni = 0; ni < 2; ni++) {
                wmma::fragment<wmma::matrix_b, 16, 16, 8, wmma::precision::tf32, wmma::row_major> bh, bl;
                wmma::load_matrix_sync(bh, &Bhs[cur][ks][nw + ni * 16], SKB);
                wmma::load_matrix_sync(bl, &Bls[cur][ks][nw + ni * 16], SKB);
#pragma unroll
                for (int mi = 0; mi < 2; mi++) {
                    wmma::mma_sync(cfr[mi][ni], ah[mi], bh, cfr[mi][ni]);
                    wmma::mma_sync(cfr[mi][ni], al[mi], bh, cfr[mi][ni]);
                    wmma::mma_sync(cfr[mi][ni], ah[mi], bl, cfr[mi][ni]);
                }
            }
        }

        if (hasNext) {
            stA(cur ^ 1); stB(cur ^ 1);
            __syncthreads();
            cur ^= 1;
        }
    }

    // ---- epilogue ----
#pragma unroll
    for (int mi = 0; mi < 2; mi++) {
        int gm = m0 + mw + mi * 16;
#pragma unroll
        for (int ni = 0; ni < 2; ni++) {
            if (relu) {
#pragma unroll
                for (int q = 0; q < cfr[mi][ni].num_elements; q++)
                    cfr[mi][ni].x[q] = fmaxf(cfr[mi][ni].x[q], 0.f);
            }
            wmma::store_matrix_sync(&C[(size_t)gm * N + n0 + nw + ni * 16], cfr[mi][ni], N,
                                    wmma::mem_row_major);
        }
    }
}

// ---------------- weight split / pack kernels (run once per use, tiny) ----------------
__global__ void split_plain_kernel(const float* __restrict__ src,
                                   float* __restrict__ bh, float* __restrict__ bl, int n)
{
    int i = blockIdx.x * 256 + threadIdx.x;
    if (i >= n) return;
    float v = src[i];
    float h = to_tf32(v);
    bh[i] = h;
    bl[i] = to_tf32(v - h);
}

// gat_W[4][64][256] -> packed [2][64][512]: type 0 (src=w): rel0|rel2, type 1 (src=t): rel1|rel3
__global__ void pack_gat_kernel(const float* __restrict__ W,
                                float* __restrict__ bh, float* __restrict__ bl)
{
    int idx = blockIdx.x * 256 + threadIdx.x;
    if (idx >= 65536) return;
    int s = idx >> 15;
    int rem = idx & 32767;
    int k = rem >> 9;
    int c = rem & 511;
    int rel = (s ? 1 : 0) + ((c >= 256) ? 2 : 0);
    float v = W[(size_t)rel * 16384 + k * 256 + (c & 255)];
    float h = to_tf32(v);
    bh[idx] = h;
    bl[idx] = to_tf32(v - h);
}

// Wn[4][256][64] -> packed [2][256][128]: type 0 (src=w): rel0|rel2, type 1 (src=t): rel1|rel3
__global__ void pack_wn_kernel(const float* __restrict__ Wn,
                               float* __restrict__ bh, float* __restrict__ bl)
{
    int idx = blockIdx.x * 256 + threadIdx.x;
    if (idx >= 65536) return;
    int s = idx >> 15;
    int rem = idx & 32767;
    int k = rem >> 7;
    int c = rem & 127;
    int rel = (s ? 1 : 0) + ((c >= 64) ? 2 : 0);
    float v = Wn[(size_t)rel * 16384 + k * 64 + (c & 63)];
    float h = to_tf32(v);
    bh[idx] = h;
    bl[idx] = to_tf32(v - h);
}

// Ws sums (rel0+rel2 for t-self, rel1+rel3 for w-self) -> split [2][256][64]; bias sums fp32
__global__ void wsum_split_kernel(const float* __restrict__ Ws, const float* __restrict__ b,
                                  float* __restrict__ bh, float* __restrict__ bl,
                                  float* __restrict__ bsum)
{
    int i = blockIdx.x * 256 + threadIdx.x;
    if (i < 32768) {
        int s = i >> 14;
        int j = i & 16383;
        float v = s ? (Ws[16384 + j] + Ws[3 * 16384 + j]) : (Ws[j] + Ws[2 * 16384 + j]);
        float h = to_tf32(v);
        bh[i] = h;
        bl[i] = to_tf32(v - h);
    }
    if (i < 64) bsum[i] = b[i] + b[2 * 64 + i];
    else if (i < 128) { int j = i - 64; bsum[i] = b[64 + j] + b[3 * 64 + j]; }
}

// ------------- fold attention vectors into K-side: v[k,h] = sum_d W[k, h*64+d]*a[h,d] --------
__global__ void attnvec_kernel(const float* __restrict__ W, const float* __restrict__ al,
                               const float* __restrict__ ar,
                               float* __restrict__ alv, float* __restrict__ arv)
{
    int idx = blockIdx.x * 256 + threadIdx.x;      // 2048 total
    if (idx >= 2048) return;
    int type = idx >> 10;
    int rem = idx & 1023;
    int r = rem >> 8;
    int k = (rem >> 2) & 63;
    int h = rem & 3;
    const float* av = type ? ar : al;
    float s = 0.f;
#pragma unroll 16
    for (int d = 0; d < 64; d++)
        s += W[(size_t)r * 16384 + (size_t)k * 256 + h * 64 + d] * av[r * 256 + h * 64 + d];
    (type ? arv : alv)[r * 256 + k * 4 + h] = s;
}

// ------------- fused el/er projection: one X read computes 4 vec-projections -------------
__global__ void vecproj_fused_kernel(const float* __restrict__ Xt, const float* __restrict__ Xw,
                                     const float* __restrict__ alv, const float* __restrict__ arv,
                                     float* __restrict__ el, float* __restrict__ er,
                                     int NT, int NW)
{
    int type = blockIdx.y;                 // 0 = tx nodes, 1 = w nodes
    const float* X = type ? Xw : Xt;
    int n = type ? NW : NT;
    int e0 = type ? 0 : 1;                 // el relations {e0, e0+2} (this type is src)
    int r0 = type ? 1 : 0;                 // er relations {r0, r0+2} (this type is dst)

    __shared__ float sv[4][256];
    for (int i = threadIdx.x; i < 1024; i += blockDim.x) {
        int v = i >> 8, c = i & 255;
        const float* src = (v < 2) ? (alv + (e0 + 2 * (v & 1)) * 256)
                                   : (arv + (r0 + 2 * (v & 1)) * 256);
        sv[v][c] = src[c];
    }
    __syncthreads();
    int i = blockIdx.x * blockDim.x + threadIdx.x;
    if (i >= n) return;
    const float* x = X + (size_t)i * 64;
    float a[4][4] = {};
#pragma unroll 8
    for (int k = 0; k < 64; k++) {
        float xv = __ldg(&x[k]);
#pragma unroll
        for (int v = 0; v < 4; v++) {
            float4 s4 = *(const float4*)&sv[v][k * 4];
            a[v][0] += xv * s4.x; a[v][1] += xv * s4.y;
            a[v][2] += xv * s4.z; a[v][3] += xv * s4.w;
        }
    }
    *(float4*)&el[(size_t)(e0)     * MAXN * 4 + (size_t)i * 4] = make_float4(a[0][0], a[0][1], a[0][2], a[0][3]);
    *(float4*)&el[(size_t)(e0 + 2) * MAXN * 4 + (size_t)i * 4] = make_float4(a[1][0], a[1][1], a[1][2], a[1][3]);
    *(float4*)&er[(size_t)(r0)     * MAXN * 4 + (size_t)i * 4] = make_float4(a[2][0], a[2][1], a[2][2], a[2][3]);
    *(float4*)&er[(size_t)(r0 + 2) * MAXN * 4 + (size_t)i * 4] = make_float4(a[3][0], a[3][1], a[3][2], a[3][3]);
}

// ---------------- CSR build ----------------
__global__ void hist_kernel(const int* __restrict__ edges, int* __restrict__ cnt, int E, int n)
{
    for (int idx = blockIdx.x * blockDim.x + threadIdx.x; idx < 4 * E; idx += gridDim.x * blockDim.x) {
        int r = idx / E, i = idx - r * E;
        int dst = edges[(size_t)(2 * r + 1) * E + i];
        atomicAdd(&cnt[r * n + dst], 1);
    }
}

__global__ void scan_kernel(const int* __restrict__ cnt, int* __restrict__ rp, int n)
{
    int r = blockIdx.x;
    int t = threadIdx.x;                      // 1024 threads
    int C = (n + 1023) / 1024;
    __shared__ int sums[1024];
    int base = t * C;
    int loc = 0;
    for (int i = 0; i < C; i++) {
        int idx = base + i;
        if (idx < n) loc += cnt[r * n + idx];
    }
    sums[t] = loc;
    __syncthreads();
    for (int off = 1; off < 1024; off <<= 1) {
        int v = (t >= off) ? sums[t - off] : 0;
        __syncthreads();
        sums[t] += v;
        __syncthreads();
    }
    int run = (t == 0) ? 0 : sums[t - 1];
    for (int i = 0; i < C; i++) {
        int idx = base + i;
        if (idx < n) {
            rp[(size_t)r * (n + 1) + idx] = run;
            run += cnt[r * n + idx];
        }
    }
    if (t == 1023) rp[(size_t)r * (n + 1) + n] = sums[1023];
}

__global__ void scatter_kernel(const int* __restrict__ edges, int* __restrict__ cnt,
                               const int* __restrict__ rp, int* __restrict__ col, int E, int n)
{
    for (int idx = blockIdx.x * blockDim.x + threadIdx.x; idx < 4 * E; idx += gridDim.x * blockDim.x) {
        int r = idx / E, i = idx - r * E;
        int src = edges[(size_t)(2 * r) * E + i];
        int dst = edges[(size_t)(2 * r + 1) * E + i];
        int pos = rp[(size_t)r * (n + 1) + dst] + atomicAdd(&cnt[r * n + dst], 1);
        col[(size_t)r * E + pos] = src;
    }
}

// ---------------- GAT aggregation: warp per dst, packed H [n_src][512] ----------------
__device__ __forceinline__ float lrelu(float x) { return x > 0.f ? x : 0.2f * x; }

__global__ void gat_agg_kernel(float* __restrict__ Ot, float* __restrict__ Ow,
                               const float* __restrict__ Hw, const float* __restrict__ Ht,
                               const float* __restrict__ el, const float* __restrict__ er,
                               const int* __restrict__ rp, const int* __restrict__ col,
                               const float* __restrict__ gb, int NT, int NW, int E)
{
    const size_t EO4 = (size_t)MAXN * 4;
    int yt = blockIdx.y;                 // 0 = tx dst (rel 0,2; src w), 1 = w dst (rel 1,3; src t)
    int n = yt ? NW : NT;
    float* out = yt ? Ow : Ot;
    const float* H = yt ? Ht : Hw;       // packed: rel ra at cols 0-255, rel rb at cols 256-511
    int ra = yt, rb = yt + 2;

    int w = (blockIdx.x * blockDim.x + threadIdx.x) >> 5;
    int lane = threadIdx.x & 31;
    if (w >= n) return;

    float4 acc0 = make_float4(0.f, 0.f, 0.f, 0.f);
    float4 acc1 = make_float4(0.f, 0.f, 0.f, 0.f);

#pragma unroll
    for (int q = 0; q < 2; q++) {
        int rel = q ? rb : ra;
        const float* elr = el + (size_t)rel * EO4;
        const float* err = er + (size_t)rel * EO4;
        const int* rpr   = rp + (size_t)rel * (MAXN + 1);
        const int* colr  = col + (size_t)rel * E;
        const float* Hq  = H + q * 256;

        int s0 = rpr[w], s1 = rpr[w + 1];
        if (s1 <= s0) continue;

        float4 e4 = *(const float4*)(err + (size_t)w * 4);
        float er0 = e4.x, er1 = e4.y, er2 = e4.z, er3 = e4.w;

        float m0 = -1e30f, m1 = -1e30f, m2 = -1e30f, m3 = -1e30f;
        for (int e = s0 + lane; e < s1; e += 32) {
            int s = colr[e];
            float4 l4 = *(const float4*)(elr + (size_t)s * 4);
            m0 = fmaxf(m0, lrelu(l4.x + er0));
            m1 = fmaxf(m1, lrelu(l4.y + er1));
            m2 = fmaxf(m2, lrelu(l4.z + er2));
            m3 = fmaxf(m3, lrelu(l4.w + er3));
        }
#pragma unroll
        for (int o = 16; o; o >>= 1) {
            m0 = fmaxf(m0, __shfl_xor_sync(0xffffffffu, m0, o));
            m1 = fmaxf(m1, __shfl_xor_sync(0xffffffffu, m1, o));
            m2 = fmaxf(m2, __shfl_xor_sync(0xffffffffu, m2, o));
            m3 = fmaxf(m3, __shfl_xor_sync(0xffffffffu, m3, o));
        }
        float z0 = 0, z1 = 0, z2 = 0, z3 = 0;
        for (int e = s0 + lane; e < s1; e += 32) {
            int s = colr[e];
            float4 l4 = *(const float4*)(elr + (size_t)s * 4);
            z0 += __expf(lrelu(l4.x + er0) - m0);
            z1 += __expf(lrelu(l4.y + er1) - m1);
            z2 += __expf(lrelu(l4.z + er2) - m2);
            z3 += __expf(lrelu(l4.w + er3) - m3);
        }
#pragma unroll
        for (int o = 16; o; o >>= 1) {
            z0 += __shfl_xor_sync(0xffffffffu, z0, o);
            z1 += __shfl_xor_sync(0xffffffffu, z1, o);
            z2 += __shfl_xor_sync(0xffffffffu, z2, o);
            z3 += __shfl_xor_sync(0xffffffffu, z3, o);
        }
        float i0 = 1.f / z0, i1 = 1.f / z1, i2 = 1.f / z2, i3 = 1.f / z3;

        for (int e = s0; e < s1; e++) {
            int s = colr[e];
            float4 l4 = *(const float4*)(elr + (size_t)s * 4);
            float a0 = __expf(lrelu(l4.x + er0) - m0) * i0;
            float a1 = __expf(lrelu(l4.y + er1) - m1) * i1;
            float a2 = __expf(lrelu(l4.z + er2) - m2) * i2;
            float a3 = __expf(lrelu(l4.w + er3) - m3) * i3;
            float wA = (lane < 16) ? a0 : a1;
            float wB = (lane < 16) ? a2 : a3;
            const float4* hp = (const float4*)(Hq + (size_t)s * 512);
            float4 h0 = hp[lane];
            float4 h1 = hp[lane + 32];
            acc0.x = fmaf(wA, h0.x, acc0.x); acc0.y = fmaf(wA, h0.y, acc0.y);
            acc0.z = fmaf(wA, h0.z, acc0.z); acc0.w = fmaf(wA, h0.w, acc0.w);
            acc1.x = fmaf(wB, h1.x, acc1.x); acc1.y = fmaf(wB, h1.y, acc1.y);
            acc1.z = fmaf(wB, h1.z, acc1.z); acc1.w = fmaf(wB, h1.w, acc1.w);
        }
    }

    const float4* ba4 = (const float4*)(gb + (size_t)ra * 256);
    const float4* bb4 = (const float4*)(gb + (size_t)rb * 256);
    float4* op = (float4*)(out + (size_t)w * 256);
    {
        float4 x = ba4[lane], y = bb4[lane];
        float4 o;
        o.x = fmaxf(0.f, 0.5f * acc0.x + 0.5f * (x.x + y.x));
        o.y = fmaxf(0.f, 0.5f * acc0.y + 0.5f * (x.y + y.y));
        o.z = fmaxf(0.f, 0.5f * acc0.z + 0.5f * (x.z + y.z));
        o.w = fmaxf(0.f, 0.5f * acc0.w + 0.5f * (x.w + y.w));
        op[lane] = o;
    }
    {
        float4 x = ba4[lane + 32], y = bb4[lane + 32];
        float4 o;
        o.x = fmaxf(0.f, 0.5f * acc1.x + 0.5f * (x.x + y.x));
        o.y = fmaxf(0.f, 0.5f * acc1.y + 0.5f * (x.y + y.y));
        o.z = fmaxf(0.f, 0.5f * acc1.z + 0.5f * (x.z + y.z));
        o.w = fmaxf(0.f, 0.5f * acc1.w + 0.5f * (x.w + y.w));
        op[lane + 32] = o;
    }
}

// ------------- SAGE1 combine: X = relu(X + mean_a(Y[:,0:64]) + mean_b(Y[:,64:128])) ----------
__global__ void sage1_combine_kernel(float* __restrict__ X, const float* __restrict__ Y,
    const int* __restrict__ rpa, const int* __restrict__ cola,
    const int* __restrict__ rpb, const int* __restrict__ colb, int n)
{
    int w = (blockIdx.x * blockDim.x + threadIdx.x) >> 5;
    int lane = threadIdx.x & 31;
    if (w >= n) return;
    float mx = 0.f, my = 0.f;
    {
        int s0 = rpa[w], s1 = rpa[w + 1];
        float sx = 0.f, sy = 0.f;
        for (int e = s0; e < s1; e++) {
            int s = cola[e];
            float2 v = *(const float2*)&Y[(size_t)s * 128 + lane * 2];
            sx += v.x; sy += v.y;
        }
        float inv = 1.f / fmaxf((float)(s1 - s0), 1.f);
        mx += sx * inv; my += sy * inv;
    }
    {
        int s0 = rpb[w], s1 = rpb[w + 1];
        float sx = 0.f, sy = 0.f;
        for (int e = s0; e < s1; e++) {
            int s = colb[e];
            float2 v = *(const float2*)&Y[(size_t)s * 128 + 64 + lane * 2];
            sx += v.x; sy += v.y;
        }
        float inv = 1.f / fmaxf((float)(s1 - s0), 1.f);
        mx += sx * inv; my += sy * inv;
    }
    float2* xp = (float2*)&X[(size_t)w * 64 + lane * 2];
    float2 xv = *xp;
    xv.x = fmaxf(xv.x + mx, 0.f);
    xv.y = fmaxf(xv.y + my, 0.f);
    *xp = xv;
}

// ------------- SAGE2 projections: self (Ws_a+Ws_b) and two y = X@Wn, all dim 2 -------------
__global__ void proj6_kernel(const float* __restrict__ X,
    const float* __restrict__ WsA, const float* __restrict__ WsB,
    const float* __restrict__ WnA, const float* __restrict__ WnB,
    float* __restrict__ selfO, float* __restrict__ yA, float* __restrict__ yB, int n)
{
    __shared__ float sw[3][512];
    for (int i = threadIdx.x; i < 512; i += blockDim.x) {
        sw[0][i] = WsA[i] + WsB[i];
        sw[1][i] = WnA[i];
        sw[2][i] = WnB[i];
    }
    __syncthreads();
    int w = (blockIdx.x * blockDim.x + threadIdx.x) >> 5;
    int lane = threadIdx.x & 31;
    if (w >= n) return;
    float a[6] = {0.f, 0.f, 0.f, 0.f, 0.f, 0.f};
    for (int k = lane; k < 256; k += 32) {
        float x = X[(size_t)w * 256 + k];
        a[0] += x * sw[0][2 * k]; a[1] += x * sw[0][2 * k + 1];
        a[2] += x * sw[1][2 * k]; a[3] += x * sw[1][2 * k + 1];
        a[4] += x * sw[2][2 * k]; a[5] += x * sw[2][2 * k + 1];
    }
#pragma unroll
    for (int o = 16; o; o >>= 1)
#pragma unroll
        for (int j = 0; j < 6; j++)
            a[j] += __shfl_xor_sync(0xffffffffu, a[j], o);
    if (lane == 0) {
        *(float2*)&selfO[(size_t)w * 2] = make_float2(a[0], a[1]);
        *(float2*)&yA[(size_t)w * 2]    = make_float2(a[2], a[3]);
        *(float2*)&yB[(size_t)w * 2]    = make_float2(a[4], a[5]);
    }
}

// ------------- SAGE2 combine: out = self + bA + bB + mean_a(yA) + mean_b(yB) -------------
__global__ void sage2_combine_kernel(float* __restrict__ out,
    const float* __restrict__ selfO, const float* __restrict__ yA, const float* __restrict__ yB,
    const int* __restrict__ rpa, const int* __restrict__ cola,
    const int* __restrict__ rpb, const int* __restrict__ colb,
    const float* __restrict__ bA, const float* __restrict__ bB, int n)
{
    int w = blockIdx.x * blockDim.x + threadIdx.x;
    if (w >= n) return;
    float2 r = *(const float2*)&selfO[(size_t)w * 2];
    r.x += bA[0] + bB[0];
    r.y += bA[1] + bB[1];
    {
        int s0 = rpa[w], s1 = rpa[w + 1];
        float sx = 0.f, sy = 0.f;
        for (int e = s0; e < s1; e++) {
            float2 v = *(const float2*)&yA[(size_t)cola[e] * 2];
            sx += v.x; sy += v.y;
        }
        float inv = 1.f / fmaxf((float)(s1 - s0), 1.f);
        r.x += sx * inv; r.y += sy * inv;
    }
    {
        int s0 = rpb[w], s1 = rpb[w + 1];
        float sx = 0.f, sy = 0.f;
        for (int e = s0; e < s1; e++) {
            float2 v = *(const float2*)&yB[(size_t)colb[e] * 2];
            sx += v.x; sy += v.y;
        }
        float inv = 1.f / fmaxf((float)(s1 - s0), 1.f);
        r.x += sx * inv; r.y += sy * inv;
    }
    *(float2*)&out[(size_t)w * 2] = r;
}

// ---------------- host helpers ----------------
static void gemm_ts(const float* A, const float* Bh, const float* Bl, float* C,
                    const float* bias, int M, int N, int K, int relu)
{
    dim3 g(N / 64, (M + 127) / 128);
    if ((K & 15) == 0) gemm_ts_kernel<true><<<g, 256>>>(A, Bh, Bl, C, bias, M, N, K, relu);
    else               gemm_ts_kernel<false><<<g, 256>>>(A, Bh, Bl, C, bias, M, N, K, relu);
}

static void gat_layer(const float* gW, const float* gal, const float* gar, const float* gb,
                      const float* Xt, const float* Xw, float* Ot, float* Ow,
                      float* Hw, float* Ht, float* bh, float* bl,
                      float* el, float* er, float* alv, float* arv,
                      const int* rp, const int* col, int NT, int NW, int E)
{
    attnvec_kernel<<<8, 256>>>(gW, gal, gar, alv, arv);
    pack_gat_kernel<<<256, 256>>>(gW, bh, bl);
    gemm_ts(Xw, bh,         bl,         Hw, nullptr, NW, 512, 64, 0);   // src=w: rel0|rel2
    gemm_ts(Xt, bh + 32768, bl + 32768, Ht, nullptr, NT, 512, 64, 0);   // src=t: rel1|rel3
    int nmax = NT > NW ? NT : NW;
    dim3 gv((nmax + 255) / 256, 2);
    vecproj_fused_kernel<<<gv, 256>>>(Xt, Xw, alv, arv, el, er, NT, NW);
    dim3 ga((nmax + 7) / 8, 2);
    gat_agg_kernel<<<ga, 256>>>(Ot, Ow, Hw, Ht, el, er, rp, col, gb, NT, NW, E);
}

extern "C" void kernel_launch(void* const* d_in, const int* in_sizes, int n_in,
                              void* d_out, int out_size)
{
    const float* tx_feat  = (const float*)d_in[0];
    const float* w_feat   = (const float*)d_in[1];
    const int*   edges    = (const int*)d_in[2];
    const float* tx_W     = (const float*)d_in[3];
    const float* tx_b     = (const float*)d_in[4];
    const float* w_W      = (const float*)d_in[5];
    const float* w_b      = (const float*)d_in[6];
    const float* gat1_W   = (const float*)d_in[7];
    const float* gat1_al  = (const float*)d_in[8];
    const float* gat1_ar  = (const float*)d_in[9];
    const float* gat1_b   = (const float*)d_in[10];
    const float* sage1_Ws = (const float*)d_in[11];
    const float* sage1_Wn = (const float*)d_in[12];
    const float* sage1_b  = (const float*)d_in[13];
    const float* gat2_W   = (const float*)d_in[14];
    const float* gat2_al  = (const float*)d_in[15];
    const float* gat2_ar  = (const float*)d_in[16];
    const float* gat2_b   = (const float*)d_in[17];
    const float* sage2_Ws = (const float*)d_in[18];
    const float* sage2_Wn = (const float*)d_in[19];
    const float* sage2_b  = (const float*)d_in[20];

    int NT = in_sizes[0] / 166;
    int NW = in_sizes[1] / 56;
    int E  = in_sizes[2] / 8;
    if (NT > MAXN) NT = MAXN;
    if (NW > MAXN) NW = MAXN;
    if (E > MAXE) E = MAXE;

    float *t0, *w0, *t1, *w1, *hs, *el, *er, *alv, *arv, *bh, *bl, *bsum;
    int *cnt, *rp, *col;
    cudaGetSymbolAddress((void**)&t0, d_t0);
    cudaGetSymbolAddress((void**)&w0, d_w0);
    cudaGetSymbolAddress((void**)&t1, d_t1);
    cudaGetSymbolAddress((void**)&w1, d_w1);
    cudaGetSymbolAddress((void**)&hs, d_hs);
    cudaGetSymbolAddress((void**)&el, d_el);
    cudaGetSymbolAddress((void**)&er, d_er);
    cudaGetSymbolAddress((void**)&alv, d_alv);
    cudaGetSymbolAddress((void**)&arv, d_arv);
    cudaGetSymbolAddress((void**)&bh, d_bh);
    cudaGetSymbolAddress((void**)&bl, d_bl);
    cudaGetSymbolAddress((void**)&bsum, d_bsum);
    cudaGetSymbolAddress((void**)&cnt, d_cnt);
    cudaGetSymbolAddress((void**)&rp, d_rpv);
    cudaGetSymbolAddress((void**)&col, d_colv);

    float* fout = (float*)d_out;
    float* Hw = hs;                                  // packed H src=w: [MAXN][512]
    float* Ht = hs + (size_t)MAXN * 512;             // packed H src=t
    float* Yw = hs;                                  // packed Y src=w: [MAXN][128] (reuse)
    float* Yt = hs + (size_t)MAXN * 128;

    const int* rp0 = rp;  const int* rp1 = rp + (MAXN + 1);
    const int* rp2 = rp + 2 * (MAXN + 1);  const int* rp3 = rp + 3 * (MAXN + 1);
    const int* col0 = col; const int* col1 = col + (size_t)E;
    const int* col2 = col + 2 * (size_t)E; const int* col3 = col + 3 * (size_t)E;

    // ---- CSR build (per relation, dst-sorted) ----
    cudaMemsetAsync(cnt, 0, 4 * (size_t)MAXN * sizeof(int));
    hist_kernel<<<(4 * E + 255) / 256, 256>>>(edges, cnt, E, NT);
    scan_kernel<<<4, 1024>>>(cnt, rp, NT);
    cudaMemsetAsync(cnt, 0, 4 * (size_t)MAXN * sizeof(int));
    scatter_kernel<<<(4 * E + 255) / 256, 256>>>(edges, cnt, rp, col, E, NT);

    // ---- S0: input projections (relu) -> width 64 ----
    split_plain_kernel<<<(166 * 64 + 255) / 256, 256>>>(tx_W, bh, bl, 166 * 64);
    gemm_ts(tx_feat, bh, bl, t0, tx_b, NT, 64, 166, 1);
    split_plain_kernel<<<(56 * 64 + 255) / 256, 256>>>(w_W, bh, bl, 56 * 64);
    gemm_ts(w_feat, bh, bl, w0, w_b, NW, 64, 56, 1);

    // ---- S1: hetero GAT1 (64 -> 256, relu fused) ----
    gat_layer(gat1_W, gat1_al, gat1_ar, gat1_b, t0, w0, t1, w1,
              Hw, Ht, bh, bl, el, er, alv, arv, rp, col, NT, NW, E);

    // ---- S2: hetero SAGE1 (256 -> 64): project-then-aggregate ----
    {
        wsum_split_kernel<<<128, 256>>>(sage1_Ws, sage1_b, bh, bl, bsum);
        gemm_ts(t1, bh,         bl,         t0, bsum,      NT, 64, 256, 0);
        gemm_ts(w1, bh + 16384, bl + 16384, w0, bsum + 64, NW, 64, 256, 0);
        pack_wn_kernel<<<256, 256>>>(sage1_Wn, bh, bl);
        gemm_ts(w1, bh,         bl,         Yw, nullptr, NW, 128, 256, 0);  // src=w: rel0|rel2
        gemm_ts(t1, bh + 32768, bl + 32768, Yt, nullptr, NT, 128, 256, 0);  // src=t: rel1|rel3
        sage1_combine_kernel<<<(NT + 7) / 8, 256>>>(t0, Yw, rp0, col0, rp2, col2, NT);
        sage1_combine_kernel<<<(NW + 7) / 8, 256>>>(w0, Yt, rp1, col1, rp3, col3, NW);
    }

    // ---- S3: hetero GAT2 (64 -> 256, relu fused) ----
    gat_layer(gat2_W, gat2_al, gat2_ar, gat2_b, t0, w0, t1, w1,
              Hw, Ht, bh, bl, el, er, alv, arv, rp, col, NT, NW, E);

    // ---- S4: hetero SAGE2 (256 -> 2): project-then-aggregate ----
    {
        const size_t Y2 = (size_t)MAXN * 2;
        float* y0 = el + 0 * Y2;  float* y1 = el + 1 * Y2;
        float* y2 = el + 2 * Y2;  float* y3 = el + 3 * Y2;
        float* selfT = er + 0 * Y2;
        float* selfW = er + 1 * Y2;
        proj6_kernel<<<(NT + 7) / 8, 256>>>(t1, sage2_Ws + 0 * 512, sage2_Ws + 2 * 512,
                                            sage2_Wn + 1 * 512, sage2_Wn + 3 * 512,
                                            selfT, y1, y3, NT);
        proj6_kernel<<<(NW + 7) / 8, 256>>>(w1, sage2_Ws + 1 * 512, sage2_Ws + 3 * 512,
                                            sage2_Wn + 0 * 512, sage2_Wn + 2 * 512,
                                            selfW, y0, y2, NW);
        sage2_combine_kernel<<<(NT + 255) / 256, 256>>>(fout, selfT, y0, y2,
            rp0, col0, rp2, col2, sage2_b + 0, sage2_b + 4, NT);
        sage2_combine_kernel<<<(NW + 255) / 256, 256>>>(fout + (size_t)NT * 2, selfW, y1, y3,
            rp1, col1, rp3, col3, sage2_b + 2, sage2_b + 6, NW);
    }
}

// round 8
// speedup vs baseline: 1.1640x; 1.1608x over previous
#include <cuda_runtime.h>
#include <cuda_bf16.h>
#include <mma.h>
#include <cstdint>
#include <cstddef>

using namespace nvcuda;

#define MAXN 50000
#define MAXE 400000
#define PAD_ROWS 128

// ---------------- persistent device scratch (padded for unguarded GEMM tail stores) ------------
__device__ float d_t0[((size_t)MAXN + PAD_ROWS) * 256];
__device__ float d_w0[((size_t)MAXN + PAD_ROWS) * 256];
__device__ float d_t1[((size_t)MAXN + PAD_ROWS) * 256];
__device__ float d_w1[((size_t)MAXN + PAD_ROWS) * 256];
__device__ float d_hs[(size_t)MAXN * 1024 + PAD_ROWS * 512];  // packed H (2 x [MAXN,512]) / packed Y
__device__ float d_el[4 * (size_t)MAXN * 4];
__device__ float d_er[4 * (size_t)MAXN * 4];
__device__ float d_alv[4 * 64 * 4];
__device__ float d_arv[4 * 64 * 4];
__device__ __nv_bfloat16 d_bh16[65536];
__device__ __nv_bfloat16 d_bl16[65536];
__device__ float d_bsum[128];
__device__ int   d_cnt[4 * MAXN];
__device__ int   d_rpv[4 * (MAXN + 1)];
__device__ int   d_colv[4 * MAXE];

__device__ __forceinline__ void bf16_split(float v, __nv_bfloat16& h, __nv_bfloat16& l)
{
    h = __float2bfloat16(v);
    l = __float2bfloat16(v - __bfloat162float(h));
}

// ---------------- BF16 split tensor-core GEMM with pre-split B ----------------
// C[M,N] = A[M,K] @ B[K,N] (+bias)(relu). B given as bf16 hi/lo pair in global.
// A split to bf16 hi/lo at smem-store time (once per element per block).
// BM=128, BN=64, BK=16, 256 threads (8 warps 4x2), wmma m16n16k16, 3-term split:
// Ah*Bh + Al*Bh + Ah*Bl  (error ~2^-16). Tail rows stored unguarded (padded C).
template<bool VEC>
__launch_bounds__(256, 2)
__global__ void gemm_bs_kernel(const float* __restrict__ A,
                               const __nv_bfloat16* __restrict__ Bh,
                               const __nv_bfloat16* __restrict__ Bl,
                               float* __restrict__ C, const float* __restrict__ bias,
                               int M, int N, int K, int relu)
{
    constexpr int BM = 128, BN = 64, SKA = 32, SKB = 80;
    __shared__ __nv_bfloat16 Ahs[2][BM][SKA];
    __shared__ __nv_bfloat16 Als[2][BM][SKA];
    __shared__ __nv_bfloat16 Bhs[2][16][SKB];
    __shared__ __nv_bfloat16 Bls[2][16][SKB];
    __shared__ float Brep[16][BN];

    const int tid = threadIdx.x;
    const int wid = tid >> 5;
    const int wm = wid & 3, wn = wid >> 2;          // 4 x 2 warp grid
    const int m0 = blockIdx.y * BM, n0 = blockIdx.x * BN;
    const int mw = wm * 32;                          // warp tile: 32 rows x 32 cols
    const int nw = wn * 32;

    float4 ra4[2];  float ras[8];
    uint2 rbh2;     __nv_bfloat16 rbhs[4];
    uint2 rbl2;     __nv_bfloat16 rbls[4];

    auto ldA = [&](int t) {
        int k0 = t * 16;
        if (VEC) {
#pragma unroll
            for (int i = 0; i < 2; i++) {
                int idx = tid + i * 256;
                int r = idx >> 2, c4 = idx & 3;
                int gm = m0 + r;
                ra4[i] = (gm < M) ? *(const float4*)&A[(size_t)gm * K + k0 + c4 * 4]
                                  : make_float4(0.f, 0.f, 0.f, 0.f);
            }
        } else {
#pragma unroll
            for (int i = 0; i < 8; i++) {
                int idx = tid + i * 256;
                int r = idx >> 4, c = idx & 15;
                int gm = m0 + r;
                ras[i] = (gm < M && k0 + c < K) ? A[(size_t)gm * K + k0 + c] : 0.f;
            }
        }
    };
    auto stA = [&](int st) {
        if (VEC) {
#pragma unroll
            for (int i = 0; i < 2; i++) {
                int idx = tid + i * 256;
                int r = idx >> 2, c4 = idx & 3;
                float v[4] = {ra4[i].x, ra4[i].y, ra4[i].z, ra4[i].w};
#pragma unroll
                for (int j = 0; j < 4; j++) {
                    __nv_bfloat16 h, l;
                    bf16_split(v[j], h, l);
                    Ahs[st][r][c4 * 4 + j] = h;
                    Als[st][r][c4 * 4 + j] = l;
                }
            }
        } else {
#pragma unroll
            for (int i = 0; i < 8; i++) {
                int idx = tid + i * 256;
                int r = idx >> 4, c = idx & 15;
                __nv_bfloat16 h, l;
                bf16_split(ras[i], h, l);
                Ahs[st][r][c] = h;
                Als[st][r][c] = l;
            }
        }
    };
    auto ldB = [&](int t) {
        int k0 = t * 16;
        if (VEC) {
            int r = tid >> 4, c4 = tid & 15;         // 16 rows x 64 cols, 4 bf16/thread
            rbh2 = *(const uint2*)&Bh[(size_t)(k0 + r) * N + n0 + c4 * 4];
            rbl2 = *(const uint2*)&Bl[(size_t)(k0 + r) * N + n0 + c4 * 4];
        } else {
#pragma unroll
            for (int i = 0; i < 4; i++) {
                int idx = tid + i * 256;
                int r = idx >> 6, c = idx & 63;
                bool ok = (k0 + r) < K;
                rbhs[i] = ok ? Bh[(size_t)(k0 + r) * N + n0 + c] : __float2bfloat16(0.f);
                rbls[i] = ok ? Bl[(size_t)(k0 + r) * N + n0 + c] : __float2bfloat16(0.f);
            }
        }
    };
    auto stB = [&](int st) {
        if (VEC) {
            int r = tid >> 4, c4 = tid & 15;
            *(uint2*)&Bhs[st][r][c4 * 4] = rbh2;
            *(uint2*)&Bls[st][r][c4 * 4] = rbl2;
        } else {
#pragma unroll
            for (int i = 0; i < 4; i++) {
                int idx = tid + i * 256;
                int r = idx >> 6, c = idx & 63;
                Bhs[st][r][c] = rbhs[i];
                Bls[st][r][c] = rbls[i];
            }
        }
    };

    // ---- prologue ----
    ldA(0); ldB(0);
    stA(0); stB(0);
    if (bias) {
        for (int i = tid; i < 16 * BN; i += 256)
            Brep[i >> 6][i & 63] = bias[n0 + (i & 63)];
    }
    __syncthreads();

    wmma::fragment<wmma::accumulator, 16, 16, 16, float> cfr[2][2];
#pragma unroll
    for (int mi = 0; mi < 2; mi++)
#pragma unroll
        for (int ni = 0; ni < 2; ni++) {
            if (bias)
                wmma::load_matrix_sync(cfr[mi][ni], &Brep[0][nw + ni * 16], BN, wmma::mem_row_major);
            else
                wmma::fill_fragment(cfr[mi][ni], 0.f);
        }

    const int numK = (K + 15) >> 4;
    int cur = 0;
    for (int t = 0; t < numK; t++) {
        bool hasNext = (t + 1 < numK);
        if (hasNext) { ldA(t + 1); ldB(t + 1); }

        wmma::fragment<wmma::matrix_a, 16, 16, 16, __nv_bfloat16, wmma::row_major> fah[2], fal[2];
#pragma unroll
        for (int mi = 0; mi < 2; mi++) {
            wmma::load_matrix_sync(fah[mi], &Ahs[cur][mw + mi * 16][0], SKA);
            wmma::load_matrix_sync(fal[mi], &Als[cur][mw + mi * 16][0], SKA);
        }
#pragma unroll
        for (int ni = 0; ni < 2; ni++) {
            wmma::fragment<wmma::matrix_b, 16, 16, 16, __nv_bfloat16, wmma::row_major> fbh, fbl;
            wmma::load_matrix_sync(fbh, &Bhs[cur][0][nw + ni * 16], SKB);
            wmma::load_matrix_sync(fbl, &Bls[cur][0][nw + ni * 16], SKB);
#pragma unroll
            for (int mi = 0; mi < 2; mi++) {
                wmma::mma_sync(cfr[mi][ni], fah[mi], fbh, cfr[mi][ni]);
                wmma::mma_sync(cfr[mi][ni], fal[mi], fbh, cfr[mi][ni]);
                wmma::mma_sync(cfr[mi][ni], fah[mi], fbl, cfr[mi][ni]);
            }
        }

        if (hasNext) {
            stA(cur ^ 1); stB(cur ^ 1);
            __syncthreads();
            cur ^= 1;
        }
    }

    // ---- epilogue ----
#pragma unroll
    for (int mi = 0; mi < 2; mi++) {
        int gm = m0 + mw + mi * 16;
#pragma unroll
        for (int ni = 0; ni < 2; ni++) {
            if (relu) {
#pragma unroll
                for (int q = 0; q < cfr[mi][ni].num_elements; q++)
                    cfr[mi][ni].x[q] = fmaxf(cfr[mi][ni].x[q], 0.f);
            }
            wmma::store_matrix_sync(&C[(size_t)gm * N + n0 + nw + ni * 16], cfr[mi][ni], N,
                                    wmma::mem_row_major);
        }
    }
}

// ---------------- weight split / pack kernels (tiny) ----------------
__global__ void split_plain_kernel(const float* __restrict__ src,
                                   __nv_bfloat16* __restrict__ bh,
                                   __nv_bfloat16* __restrict__ bl, int n)
{
    int i = blockIdx.x * 256 + threadIdx.x;
    if (i >= n) return;
    __nv_bfloat16 h, l;
    bf16_split(src[i], h, l);
    bh[i] = h; bl[i] = l;
}

// gat_W[4][64][256] -> packed [2][64][512]: type 0 (src=w): rel0|rel2, type 1 (src=t): rel1|rel3
__global__ void pack_gat_kernel(const float* __restrict__ W,
                                __nv_bfloat16* __restrict__ bh, __nv_bfloat16* __restrict__ bl)
{
    int idx = blockIdx.x * 256 + threadIdx.x;
    if (idx >= 65536) return;
    int s = idx >> 15;
    int rem = idx & 32767;
    int k = rem >> 9;
    int c = rem & 511;
    int rel = (s ? 1 : 0) + ((c >= 256) ? 2 : 0);
    __nv_bfloat16 h, l;
    bf16_split(W[(size_t)rel * 16384 + k * 256 + (c & 255)], h, l);
    bh[idx] = h; bl[idx] = l;
}

// Wn[4][256][64] -> packed [2][256][128]: type 0 (src=w): rel0|rel2, type 1 (src=t): rel1|rel3
__global__ void pack_wn_kernel(const float* __restrict__ Wn,
                               __nv_bfloat16* __restrict__ bh, __nv_bfloat16* __restrict__ bl)
{
    int idx = blockIdx.x * 256 + threadIdx.x;
    if (idx >= 65536) return;
    int s = idx >> 15;
    int rem = idx & 32767;
    int k = rem >> 7;
    int c = rem & 127;
    int rel = (s ? 1 : 0) + ((c >= 64) ? 2 : 0);
    __nv_bfloat16 h, l;
    bf16_split(Wn[(size_t)rel * 16384 + k * 64 + (c & 63)], h, l);
    bh[idx] = h; bl[idx] = l;
}

// Ws sums (rel0+rel2 for t-self, rel1+rel3 for w-self) -> split [2][256][64]; bias sums fp32
__global__ void wsum_split_kernel(const float* __restrict__ Ws, const float* __restrict__ b,
                                  __nv_bfloat16* __restrict__ bh, __nv_bfloat16* __restrict__ bl,
                                  float* __restrict__ bsum)
{
    int i = blockIdx.x * 256 + threadIdx.x;
    if (i < 32768) {
        int s = i >> 14;
        int j = i & 16383;
        float v = s ? (Ws[16384 + j] + Ws[3 * 16384 + j]) : (Ws[j] + Ws[2 * 16384 + j]);
        __nv_bfloat16 h, l;
        bf16_split(v, h, l);
        bh[i] = h; bl[i] = l;
    }
    if (i < 64) bsum[i] = b[i] + b[2 * 64 + i];
    else if (i < 128) { int j = i - 64; bsum[i] = b[64 + j] + b[3 * 64 + j]; }
}

// ------------- fold attention vectors into K-side: v[k,h] = sum_d W[k, h*64+d]*a[h,d] --------
__global__ void attnvec_kernel(const float* __restrict__ W, const float* __restrict__ al,
                               const float* __restrict__ ar,
                               float* __restrict__ alv, float* __restrict__ arv)
{
    int idx = blockIdx.x * 256 + threadIdx.x;      // 2048 total
    if (idx >= 2048) return;
    int type = idx >> 10;
    int rem = idx & 1023;
    int r = rem >> 8;
    int k = (rem >> 2) & 63;
    int h = rem & 3;
    const float* av = type ? ar : al;
    float s = 0.f;
#pragma unroll 16
    for (int d = 0; d < 64; d++)
        s += W[(size_t)r * 16384 + (size_t)k * 256 + h * 64 + d] * av[r * 256 + h * 64 + d];
    (type ? arv : alv)[r * 256 + k * 4 + h] = s;
}

// ------------- fused el/er projection: one X read computes 4 vec-projections -------------
__global__ void vecproj_fused_kernel(const float* __restrict__ Xt, const float* __restrict__ Xw,
                                     const float* __restrict__ alv, const float* __restrict__ arv,
                                     float* __restrict__ el, float* __restrict__ er,
                                     int NT, int NW)
{
    int type = blockIdx.y;                 // 0 = tx nodes, 1 = w nodes
    const float* X = type ? Xw : Xt;
    int n = type ? NW : NT;
    int e0 = type ? 0 : 1;                 // el relations {e0, e0+2} (this type is src)
    int r0 = type ? 1 : 0;                 // er relations {r0, r0+2} (this type is dst)

    __shared__ float sv[4][256];
    for (int i = threadIdx.x; i < 1024; i += blockDim.x) {
        int v = i >> 8, c = i & 255;
        const float* src = (v < 2) ? (alv + (e0 + 2 * (v & 1)) * 256)
                                   : (arv + (r0 + 2 * (v & 1)) * 256);
        sv[v][c] = src[c];
    }
    __syncthreads();
    int i = blockIdx.x * blockDim.x + threadIdx.x;
    if (i >= n) return;
    const float* x = X + (size_t)i * 64;
    float a[4][4] = {};
#pragma unroll 8
    for (int k = 0; k < 64; k++) {
        float xv = __ldg(&x[k]);
#pragma unroll
        for (int v = 0; v < 4; v++) {
            float4 s4 = *(const float4*)&sv[v][k * 4];
            a[v][0] += xv * s4.x; a[v][1] += xv * s4.y;
            a[v][2] += xv * s4.z; a[v][3] += xv * s4.w;
        }
    }
    *(float4*)&el[(size_t)(e0)     * MAXN * 4 + (size_t)i * 4] = make_float4(a[0][0], a[0][1], a[0][2], a[0][3]);
    *(float4*)&el[(size_t)(e0 + 2) * MAXN * 4 + (size_t)i * 4] = make_float4(a[1][0], a[1][1], a[1][2], a[1][3]);
    *(float4*)&er[(size_t)(r0)     * MAXN * 4 + (size_t)i * 4] = make_float4(a[2][0], a[2][1], a[2][2], a[2][3]);
    *(float4*)&er[(size_t)(r0 + 2) * MAXN * 4 + (size_t)i * 4] = make_float4(a[3][0], a[3][1], a[3][2], a[3][3]);
}

// ---------------- CSR build ----------------
__global__ void hist_kernel(const int* __restrict__ edges, int* __restrict__ cnt, int E, int n)
{
    for (int idx = blockIdx.x * blockDim.x + threadIdx.x; idx < 4 * E; idx += gridDim.x * blockDim.x) {
        int r = idx / E, i = idx - r * E;
        int dst = edges[(size_t)(2 * r + 1) * E + i];
        atomicAdd(&cnt[r * n + dst], 1);
    }
}

__global__ void scan_kernel(const int* __restrict__ cnt, int* __restrict__ rp, int n)
{
    int r = blockIdx.x;
    int t = threadIdx.x;                      // 1024 threads
    int C = (n + 1023) / 1024;
    __shared__ int sums[1024];
    int base = t * C;
    int loc = 0;
    for (int i = 0; i < C; i++) {
        int idx = base + i;
        if (idx < n) loc += cnt[r * n + idx];
    }
    sums[t] = loc;
    __syncthreads();
    for (int off = 1; off < 1024; off <<= 1) {
        int v = (t >= off) ? sums[t - off] : 0;
        __syncthreads();
        sums[t] += v;
        __syncthreads();
    }
    int run = (t == 0) ? 0 : sums[t - 1];
    for (int i = 0; i < C; i++) {
        int idx = base + i;
        if (idx < n) {
            rp[(size_t)r * (n + 1) + idx] = run;
            run += cnt[r * n + idx];
        }
    }
    if (t == 1023) rp[(size_t)r * (n + 1) + n] = sums[1023];
}

__global__ void scatter_kernel(const int* __restrict__ edges, int* __restrict__ cnt,
                               const int* __restrict__ rp, int* __restrict__ col, int E, int n)
{
    for (int idx = blockIdx.x * blockDim.x + threadIdx.x; idx < 4 * E; idx += gridDim.x * blockDim.x) {
        int r = idx / E, i = idx - r * E;
        int src = edges[(size_t)(2 * r) * E + i];
        int dst = edges[(size_t)(2 * r + 1) * E + i];
        int pos = rp[(size_t)r * (n + 1) + dst] + atomicAdd(&cnt[r * n + dst], 1);
        col[(size_t)r * E + pos] = src;
    }
}

// ---------------- GAT aggregation: warp per dst, packed H [n_src][512] ----------------
__device__ __forceinline__ float lrelu(float x) { return x > 0.f ? x : 0.2f * x; }

__global__ void gat_agg_kernel(float* __restrict__ Ot, float* __restrict__ Ow,
                               const float* __restrict__ Hw, const float* __restrict__ Ht,
                               const float* __restrict__ el, const float* __restrict__ er,
                               const int* __restrict__ rp, const int* __restrict__ col,
                               const float* __restrict__ gb, int NT, int NW, int E)
{
    const size_t EO4 = (size_t)MAXN * 4;
    int yt = blockIdx.y;                 // 0 = tx dst (rel 0,2; src w), 1 = w dst (rel 1,3; src t)
    int n = yt ? NW : NT;
    float* out = yt ? Ow : Ot;
    const float* H = yt ? Ht : Hw;       // packed: rel ra at cols 0-255, rel rb at cols 256-511
    int ra = yt, rb = yt + 2;

    int w = (blockIdx.x * blockDim.x + threadIdx.x) >> 5;
    int lane = threadIdx.x & 31;
    if (w >= n) return;

    float4 acc0 = make_float4(0.f, 0.f, 0.f, 0.f);
    float4 acc1 = make_float4(0.f, 0.f, 0.f, 0.f);

#pragma unroll
    for (int q = 0; q < 2; q++) {
        int rel = q ? rb : ra;
        const float* elr = el + (size_t)rel * EO4;
        const float* err = er + (size_t)rel * EO4;
        const int* rpr   = rp + (size_t)rel * (MAXN + 1);
        const int* colr  = col + (size_t)rel * E;
        const float* Hq  = H + q * 256;

        int s0 = rpr[w], s1 = rpr[w + 1];
        if (s1 <= s0) continue;

        float4 e4 = *(const float4*)(err + (size_t)w * 4);
        float er0 = e4.x, er1 = e4.y, er2 = e4.z, er3 = e4.w;

        float m0 = -1e30f, m1 = -1e30f, m2 = -1e30f, m3 = -1e30f;
        for (int e = s0 + lane; e < s1; e += 32) {
            int s = colr[e];
            float4 l4 = *(const float4*)(elr + (size_t)s * 4);
            m0 = fmaxf(m0, lrelu(l4.x + er0));
            m1 = fmaxf(m1, lrelu(l4.y + er1));
            m2 = fmaxf(m2, lrelu(l4.z + er2));
            m3 = fmaxf(m3, lrelu(l4.w + er3));
        }
#pragma unroll
        for (int o = 16; o; o >>= 1) {
            m0 = fmaxf(m0, __shfl_xor_sync(0xffffffffu, m0, o));
            m1 = fmaxf(m1, __shfl_xor_sync(0xffffffffu, m1, o));
            m2 = fmaxf(m2, __shfl_xor_sync(0xffffffffu, m2, o));
            m3 = fmaxf(m3, __shfl_xor_sync(0xffffffffu, m3, o));
        }
        float z0 = 0, z1 = 0, z2 = 0, z3 = 0;
        for (int e = s0 + lane; e < s1; e += 32) {
            int s = colr[e];
            float4 l4 = *(const float4*)(elr + (size_t)s * 4);
            z0 += __expf(lrelu(l4.x + er0) - m0);
            z1 += __expf(lrelu(l4.y + er1) - m1);
            z2 += __expf(lrelu(l4.z + er2) - m2);
            z3 += __expf(lrelu(l4.w + er3) - m3);
        }
#pragma unroll
        for (int o = 16; o; o >>= 1) {
            z0 += __shfl_xor_sync(0xffffffffu, z0, o);
            z1 += __shfl_xor_sync(0xffffffffu, z1, o);
            z2 += __shfl_xor_sync(0xffffffffu, z2, o);
            z3 += __shfl_xor_sync(0xffffffffu, z3, o);
        }
        float i0 = 1.f / z0, i1 = 1.f / z1, i2 = 1.f / z2, i3 = 1.f / z3;

        for (int e = s0; e < s1; e++) {
            int s = colr[e];
            float4 l4 = *(const float4*)(elr + (size_t)s * 4);
            float a0 = __expf(lrelu(l4.x + er0) - m0) * i0;
            float a1 = __expf(lrelu(l4.y + er1) - m1) * i1;
            float a2 = __expf(lrelu(l4.z + er2) - m2) * i2;
            float a3 = __expf(lrelu(l4.w + er3) - m3) * i3;
            float wA = (lane < 16) ? a0 : a1;
            float wB = (lane < 16) ? a2 : a3;
            const float4* hp = (const float4*)(Hq + (size_t)s * 512);
            float4 h0 = hp[lane];
            float4 h1 = hp[lane + 32];
            acc0.x = fmaf(wA, h0.x, acc0.x); acc0.y = fmaf(wA, h0.y, acc0.y);
            acc0.z = fmaf(wA, h0.z, acc0.z); acc0.w = fmaf(wA, h0.w, acc0.w);
            acc1.x = fmaf(wB, h1.x, acc1.x); acc1.y = fmaf(wB, h1.y, acc1.y);
            acc1.z = fmaf(wB, h1.z, acc1.z); acc1.w = fmaf(wB, h1.w, acc1.w);
        }
    }

    const float4* ba4 = (const float4*)(gb + (size_t)ra * 256);
    const float4* bb4 = (const float4*)(gb + (size_t)rb * 256);
    float4* op = (float4*)(out + (size_t)w * 256);
    {
        float4 x = ba4[lane], y = bb4[lane];
        float4 o;
        o.x = fmaxf(0.f, 0.5f * acc0.x + 0.5f * (x.x + y.x));
        o.y = fmaxf(0.f, 0.5f * acc0.y + 0.5f * (x.y + y.y));
        o.z = fmaxf(0.f, 0.5f * acc0.z + 0.5f * (x.z + y.z));
        o.w = fmaxf(0.f, 0.5f * acc0.w + 0.5f * (x.w + y.w));
        op[lane] = o;
    }
    {
        float4 x = ba4[lane + 32], y = bb4[lane + 32];
        float4 o;
        o.x = fmaxf(0.f, 0.5f * acc1.x + 0.5f * (x.x + y.x));
        o.y = fmaxf(0.f, 0.5f * acc1.y + 0.5f * (x.y + y.y));
        o.z = fmaxf(0.f, 0.5f * acc1.z + 0.5f * (x.z + y.z));
        o.w = fmaxf(0.f, 0.5f * acc1.w + 0.5f * (x.w + y.w));
        op[lane + 32] = o;
    }
}

// ------------- SAGE1 combine: X = relu(X + mean_a(Y[:,0:64]) + mean_b(Y[:,64:128])) ----------
__global__ void sage1_combine_kernel(float* __restrict__ X, const float* __restrict__ Y,
    const int* __restrict__ rpa, const int* __restrict__ cola,
    const int* __restrict__ rpb, const int* __restrict__ colb, int n)
{
    int w = (blockIdx.x * blockDim.x + threadIdx.x) >> 5;
    int lane = threadIdx.x & 31;
    if (w >= n) return;
    float mx = 0.f, my = 0.f;
    {
        int s0 = rpa[w], s1 = rpa[w + 1];
        float sx = 0.f, sy = 0.f;
        for (int e = s0; e < s1; e++) {
            int s = cola[e];
            float2 v = *(const float2*)&Y[(size_t)s * 128 + lane * 2];
            sx += v.x; sy += v.y;
        }
        float inv = 1.f / fmaxf((float)(s1 - s0), 1.f);
        mx += sx * inv; my += sy * inv;
    }
    {
        int s0 = rpb[w], s1 = rpb[w + 1];
        float sx = 0.f, sy = 0.f;
        for (int e = s0; e < s1; e++) {
            int s = colb[e];
            float2 v = *(const float2*)&Y[(size_t)s * 128 + 64 + lane * 2];
            sx += v.x; sy += v.y;
        }
        float inv = 1.f / fmaxf((float)(s1 - s0), 1.f);
        mx += sx * inv; my += sy * inv;
    }
    float2* xp = (float2*)&X[(size_t)w * 64 + lane * 2];
    float2 xv = *xp;
    xv.x = fmaxf(xv.x + mx, 0.f);
    xv.y = fmaxf(xv.y + my, 0.f);
    *xp = xv;
}

// ------------- SAGE2 projections: self (Ws_a+Ws_b) and two y = X@Wn, all dim 2 -------------
__global__ void proj6_kernel(const float* __restrict__ X,
    const float* __restrict__ WsA, const float* __restrict__ WsB,
    const float* __restrict__ WnA, const float* __restrict__ WnB,
    float* __restrict__ selfO, float* __restrict__ yA, float* __restrict__ yB, int n)
{
    __shared__ float sw[3][512];
    for (int i = threadIdx.x; i < 512; i += blockDim.x) {
        sw[0][i] = WsA[i] + WsB[i];
        sw[1][i] = WnA[i];
        sw[2][i] = WnB[i];
    }
    __syncthreads();
    int w = (blockIdx.x * blockDim.x + threadIdx.x) >> 5;
    int lane = threadIdx.x & 31;
    if (w >= n) return;
    float a[6] = {0.f, 0.f, 0.f, 0.f, 0.f, 0.f};
    for (int k = lane; k < 256; k += 32) {
        float x = X[(size_t)w * 256 + k];
        a[0] += x * sw[0][2 * k]; a[1] += x * sw[0][2 * k + 1];
        a[2] += x * sw[1][2 * k]; a[3] += x * sw[1][2 * k + 1];
        a[4] += x * sw[2][2 * k]; a[5] += x * sw[2][2 * k + 1];
    }
#pragma unroll
    for (int o = 16; o; o >>= 1)
#pragma unroll
        for (int j = 0; j < 6; j++)
            a[j] += __shfl_xor_sync(0xffffffffu, a[j], o);
    if (lane == 0) {
        *(float2*)&selfO[(size_t)w * 2] = make_float2(a[0], a[1]);
        *(float2*)&yA[(size_t)w * 2]    = make_float2(a[2], a[3]);
        *(float2*)&yB[(size_t)w * 2]    = make_float2(a[4], a[5]);
    }
}

// ------------- SAGE2 combine: out = self + bA + bB + mean_a(yA) + mean_b(yB) -------------
__global__ void sage2_combine_kernel(float* __restrict__ out,
    const float* __restrict__ selfO, const float* __restrict__ yA, const float* __restrict__ yB,
    const int* __restrict__ rpa, const int* __restrict__ cola,
    const int* __restrict__ rpb, const int* __restrict__ colb,
    const float* __restrict__ bA, const float* __restrict__ bB, int n)
{
    int w = blockIdx.x * blockDim.x + threadIdx.x;
    if (w >= n) return;
    float2 r = *(const float2*)&selfO[(size_t)w * 2];
    r.x += bA[0] + bB[0];
    r.y += bA[1] + bB[1];
    {
        int s0 = rpa[w], s1 = rpa[w + 1];
        float sx = 0.f, sy = 0.f;
        for (int e = s0; e < s1; e++) {
            float2 v = *(const float2*)&yA[(size_t)cola[e] * 2];
            sx += v.x; sy += v.y;
        }
        float inv = 1.f / fmaxf((float)(s1 - s0), 1.f);
        r.x += sx * inv; r.y += sy * inv;
    }
    {
        int s0 = rpb[w], s1 = rpb[w + 1];
        float sx = 0.f, sy = 0.f;
        for (int e = s0; e < s1; e++) {
            float2 v = *(const float2*)&yB[(size_t)colb[e] * 2];
            sx += v.x; sy += v.y;
        }
        float inv = 1.f / fmaxf((float)(s1 - s0), 1.f);
        r.x += sx * inv; r.y += sy * inv;
    }
    *(float2*)&out[(size_t)w * 2] = r;
}

// ---------------- host helpers ----------------
static void gemm_bs(const float* A, const __nv_bfloat16* Bh, const __nv_bfloat16* Bl, float* C,
                    const float* bias, int M, int N, int K, int relu)
{
    dim3 g(N / 64, (M + 127) / 128);
    if ((K & 15) == 0) gemm_bs_kernel<true><<<g, 256>>>(A, Bh, Bl, C, bias, M, N, K, relu);
    else               gemm_bs_kernel<false><<<g, 256>>>(A, Bh, Bl, C, bias, M, N, K, relu);
}

static void gat_layer(const float* gW, const float* gal, const float* gar, const float* gb,
                      const float* Xt, const float* Xw, float* Ot, float* Ow,
                      float* Hw, float* Ht, __nv_bfloat16* bh, __nv_bfloat16* bl,
                      float* el, float* er, float* alv, float* arv,
                      const int* rp, const int* col, int NT, int NW, int E)
{
    attnvec_kernel<<<8, 256>>>(gW, gal, gar, alv, arv);
    pack_gat_kernel<<<256, 256>>>(gW, bh, bl);
    gemm_bs(Xw, bh,         bl,         Hw, nullptr, NW, 512, 64, 0);   // src=w: rel0|rel2
    gemm_bs(Xt, bh + 32768, bl + 32768, Ht, nullptr, NT, 512, 64, 0);   // src=t: rel1|rel3
    int nmax = NT > NW ? NT : NW;
    dim3 gv((nmax + 255) / 256, 2);
    vecproj_fused_kernel<<<gv, 256>>>(Xt, Xw, alv, arv, el, er, NT, NW);
    dim3 ga((nmax + 7) / 8, 2);
    gat_agg_kernel<<<ga, 256>>>(Ot, Ow, Hw, Ht, el, er, rp, col, gb, NT, NW, E);
}

extern "C" void kernel_launch(void* const* d_in, const int* in_sizes, int n_in,
                              void* d_out, int out_size)
{
    const float* tx_feat  = (const float*)d_in[0];
    const float* w_feat   = (const float*)d_in[1];
    const int*   edges    = (const int*)d_in[2];
    const float* tx_W     = (const float*)d_in[3];
    const float* tx_b     = (const float*)d_in[4];
    const float* w_W      = (const float*)d_in[5];
    const float* w_b      = (const float*)d_in[6];
    const float* gat1_W   = (const float*)d_in[7];
    const float* gat1_al  = (const float*)d_in[8];
    const float* gat1_ar  = (const float*)d_in[9];
    const float* gat1_b   = (const float*)d_in[10];
    const float* sage1_Ws = (const float*)d_in[11];
    const float* sage1_Wn = (const float*)d_in[12];
    const float* sage1_b  = (const float*)d_in[13];
    const float* gat2_W   = (const float*)d_in[14];
    const float* gat2_al  = (const float*)d_in[15];
    const float* gat2_ar  = (const float*)d_in[16];
    const float* gat2_b   = (const float*)d_in[17];
    const float* sage2_Ws = (const float*)d_in[18];
    const float* sage2_Wn = (const float*)d_in[19];
    const float* sage2_b  = (const float*)d_in[20];

    int NT = in_sizes[0] / 166;
    int NW = in_sizes[1] / 56;
    int E  = in_sizes[2] / 8;
    if (NT > MAXN) NT = MAXN;
    if (NW > MAXN) NW = MAXN;
    if (E > MAXE) E = MAXE;

    float *t0, *w0, *t1, *w1, *hs, *el, *er, *alv, *arv, *bsum;
    __nv_bfloat16 *bh, *bl;
    int *cnt, *rp, *col;
    cudaGetSymbolAddress((void**)&t0, d_t0);
    cudaGetSymbolAddress((void**)&w0, d_w0);
    cudaGetSymbolAddress((void**)&t1, d_t1);
    cudaGetSymbolAddress((void**)&w1, d_w1);
    cudaGetSymbolAddress((void**)&hs, d_hs);
    cudaGetSymbolAddress((void**)&el, d_el);
    cudaGetSymbolAddress((void**)&er, d_er);
    cudaGetSymbolAddress((void**)&alv, d_alv);
    cudaGetSymbolAddress((void**)&arv, d_arv);
    cudaGetSymbolAddress((void**)&bh, d_bh16);
    cudaGetSymbolAddress((void**)&bl, d_bl16);
    cudaGetSymbolAddress((void**)&bsum, d_bsum);
    cudaGetSymbolAddress((void**)&cnt, d_cnt);
    cudaGetSymbolAddress((void**)&rp, d_rpv);
    cudaGetSymbolAddress((void**)&col, d_colv);

    float* fout = (float*)d_out;
    float* Hw = hs;                                  // packed H src=w: [MAXN][512]
    float* Ht = hs + (size_t)MAXN * 512;             // packed H src=t
    float* Yw = hs;                                  // packed Y src=w: [MAXN][128] (reuse)
    float* Yt = hs + (size_t)MAXN * 128;

    const int* rp0 = rp;  const int* rp1 = rp + (MAXN + 1);
    const int* rp2 = rp + 2 * (MAXN + 1);  const int* rp3 = rp + 3 * (MAXN + 1);
    const int* col0 = col; const int* col1 = col + (size_t)E;
    const int* col2 = col + 2 * (size_t)E; const int* col3 = col + 3 * (size_t)E;

    // ---- CSR build (per relation, dst-sorted) ----
    cudaMemsetAsync(cnt, 0, 4 * (size_t)MAXN * sizeof(int));
    hist_kernel<<<(4 * E + 255) / 256, 256>>>(edges, cnt, E, NT);
    scan_kernel<<<4, 1024>>>(cnt, rp, NT);
    cudaMemsetAsync(cnt, 0, 4 * (size_t)MAXN * sizeof(int));
    scatter_kernel<<<(4 * E + 255) / 256, 256>>>(edges, cnt, rp, col, E, NT);

    // ---- S0: input projections (relu) -> width 64 ----
    split_plain_kernel<<<(166 * 64 + 255) / 256, 256>>>(tx_W, bh, bl, 166 * 64);
    gemm_bs(tx_feat, bh, bl, t0, tx_b, NT, 64, 166, 1);
    split_plain_kernel<<<(56 * 64 + 255) / 256, 256>>>(w_W, bh, bl, 56 * 64);
    gemm_bs(w_feat, bh, bl, w0, w_b, NW, 64, 56, 1);

    // ---- S1: hetero GAT1 (64 -> 256, relu fused) ----
    gat_layer(gat1_W, gat1_al, gat1_ar, gat1_b, t0, w0, t1, w1,
              Hw, Ht, bh, bl, el, er, alv, arv, rp, col, NT, NW, E);

    // ---- S2: hetero SAGE1 (256 -> 64): project-then-aggregate ----
    {
        wsum_split_kernel<<<128, 256>>>(sage1_Ws, sage1_b, bh, bl, bsum);
        gemm_bs(t1, bh,         bl,         t0, bsum,      NT, 64, 256, 0);
        gemm_bs(w1, bh + 16384, bl + 16384, w0, bsum + 64, NW, 64, 256, 0);
        pack_wn_kernel<<<256, 256>>>(sage1_Wn, bh, bl);
        gemm_bs(w1, bh,         bl,         Yw, nullptr, NW, 128, 256, 0);  // src=w: rel0|rel2
        gemm_bs(t1, bh + 32768, bl + 32768, Yt, nullptr, NT, 128, 256, 0);  // src=t: rel1|rel3
        sage1_combine_kernel<<<(NT + 7) / 8, 256>>>(t0, Yw, rp0, col0, rp2, col2, NT);
        sage1_combine_kernel<<<(NW + 7) / 8, 256>>>(w0, Yt, rp1, col1, rp3, col3, NW);
    }

    // ---- S3: hetero GAT2 (64 -> 256, relu fused) ----
    gat_layer(gat2_W, gat2_al, gat2_ar, gat2_b, t0, w0, t1, w1,
              Hw, Ht, bh, bl, el, er, alv, arv, rp, col, NT, NW, E);

    // ---- S4: hetero SAGE2 (256 -> 2): project-then-aggregate ----
    {
        const size_t Y2 = (size_t)MAXN * 2;
        float* y0 = el + 0 * Y2;  float* y1 = el + 1 * Y2;
        float* y2 = el + 2 * Y2;  float* y3 = el + 3 * Y2;
        float* selfT = er + 0 * Y2;
        float* selfW = er + 1 * Y2;
        proj6_kernel<<<(NT + 7) / 8, 256>>>(t1, sage2_Ws + 0 * 512, sage2_Ws + 2 * 512,
                                            sage2_Wn + 1 * 512, sage2_Wn + 3 * 512,
                                            selfT, y1, y3, NT);
        proj6_kernel<<<(NW + 7) / 8, 256>>>(w1, sage2_Ws + 1 * 512, sage2_Ws + 3 * 512,
                                            sage2_Wn + 0 * 512, sage2_Wn + 2 * 512,
                                            selfW, y0, y2, NW);
        sage2_combine_kernel<<<(NT + 255) / 256, 256>>>(fout, selfT, y0, y2,
            rp0, col0, rp2, col2, sage2_b + 0, sage2_b + 4, NT);
        sage2_combine_kernel<<<(NW + 255) / 256, 256>>>(fout + (size_t)NT * 2, selfW, y1, y3,
            rp1, col1, rp3, col3, sage2_b + 2, sage2_b + 6, NW);
    }
}

// round 9
// speedup vs baseline: 1.2357x; 1.0616x over previous
#include <cuda_runtime.h>
#include <cuda_bf16.h>
#include <mma.h>
#include <cstdint>
#include <cstddef>

using namespace nvcuda;

#define MAXN 50000
#define MAXE 400000
#define PAD_ROWS 128

// ---------------- persistent device scratch (padded for unguarded GEMM tail stores) ------------
__device__ float d_t0[((size_t)MAXN + PAD_ROWS) * 256];
__device__ float d_w0[((size_t)MAXN + PAD_ROWS) * 256];
__device__ float d_t1[((size_t)MAXN + PAD_ROWS) * 256];
__device__ float d_w1[((size_t)MAXN + PAD_ROWS) * 256];
__device__ float d_hs[(size_t)MAXN * 1024 + PAD_ROWS * 512];  // agg buffers / packed Y
__device__ float d_el[4 * (size_t)MAXN * 4];
__device__ float d_er[4 * (size_t)MAXN * 4];
__device__ float d_alv[4 * 64 * 4];
__device__ float d_arv[4 * 64 * 4];
__device__ __nv_bfloat16 d_bh16[65536];
__device__ __nv_bfloat16 d_bl16[65536];
__device__ float d_bsum[128];
__device__ float d_gbias[512];
__device__ int   d_cnt[4 * MAXN];
__device__ int   d_rpv[4 * (MAXN + 1)];
__device__ int   d_colv[4 * MAXE];

__device__ __forceinline__ void bf16_split(float v, __nv_bfloat16& h, __nv_bfloat16& l)
{
    h = __float2bfloat16(v);
    l = __float2bfloat16(v - __bfloat162float(h));
}

// ---------------- BF16 split tensor-core GEMM with pre-split B ----------------
// C[M,N] = A[M,K] @ B[K,N] (+bias)(relu). 3-term split: Ah*Bh + Al*Bh + Ah*Bl.
template<bool VEC>
__launch_bounds__(256, 2)
__global__ void gemm_bs_kernel(const float* __restrict__ A,
                               const __nv_bfloat16* __restrict__ Bh,
                               const __nv_bfloat16* __restrict__ Bl,
                               float* __restrict__ C, const float* __restrict__ bias,
                               int M, int N, int K, int relu)
{
    constexpr int BM = 128, BN = 64, SKA = 32, SKB = 80;
    __shared__ __nv_bfloat16 Ahs[2][BM][SKA];
    __shared__ __nv_bfloat16 Als[2][BM][SKA];
    __shared__ __nv_bfloat16 Bhs[2][16][SKB];
    __shared__ __nv_bfloat16 Bls[2][16][SKB];
    __shared__ float Brep[16][BN];

    const int tid = threadIdx.x;
    const int wid = tid >> 5;
    const int wm = wid & 3, wn = wid >> 2;
    const int m0 = blockIdx.y * BM, n0 = blockIdx.x * BN;
    const int mw = wm * 32;
    const int nw = wn * 32;

    float4 ra4[2];  float ras[8];
    uint2 rbh2;     __nv_bfloat16 rbhs[4];
    uint2 rbl2;     __nv_bfloat16 rbls[4];

    auto ldA = [&](int t) {
        int k0 = t * 16;
        if (VEC) {
#pragma unroll
            for (int i = 0; i < 2; i++) {
                int idx = tid + i * 256;
                int r = idx >> 2, c4 = idx & 3;
                int gm = m0 + r;
                ra4[i] = (gm < M) ? *(const float4*)&A[(size_t)gm * K + k0 + c4 * 4]
                                  : make_float4(0.f, 0.f, 0.f, 0.f);
            }
        } else {
#pragma unroll
            for (int i = 0; i < 8; i++) {
                int idx = tid + i * 256;
                int r = idx >> 4, c = idx & 15;
                int gm = m0 + r;
                ras[i] = (gm < M && k0 + c < K) ? A[(size_t)gm * K + k0 + c] : 0.f;
            }
        }
    };
    auto stA = [&](int st) {
        if (VEC) {
#pragma unroll
            for (int i = 0; i < 2; i++) {
                int idx = tid + i * 256;
                int r = idx >> 2, c4 = idx & 3;
                float v[4] = {ra4[i].x, ra4[i].y, ra4[i].z, ra4[i].w};
#pragma unroll
                for (int j = 0; j < 4; j++) {
                    __nv_bfloat16 h, l;
                    bf16_split(v[j], h, l);
                    Ahs[st][r][c4 * 4 + j] = h;
                    Als[st][r][c4 * 4 + j] = l;
                }
            }
        } else {
#pragma unroll
            for (int i = 0; i < 8; i++) {
                int idx = tid + i * 256;
                int r = idx >> 4, c = idx & 15;
                __nv_bfloat16 h, l;
                bf16_split(ras[i], h, l);
                Ahs[st][r][c] = h;
                Als[st][r][c] = l;
            }
        }
    };
    auto ldB = [&](int t) {
        int k0 = t * 16;
        if (VEC) {
            int r = tid >> 4, c4 = tid & 15;
            rbh2 = *(const uint2*)&Bh[(size_t)(k0 + r) * N + n0 + c4 * 4];
            rbl2 = *(const uint2*)&Bl[(size_t)(k0 + r) * N + n0 + c4 * 4];
        } else {
#pragma unroll
            for (int i = 0; i < 4; i++) {
                int idx = tid + i * 256;
                int r = idx >> 6, c = idx & 63;
                bool ok = (k0 + r) < K;
                rbhs[i] = ok ? Bh[(size_t)(k0 + r) * N + n0 + c] : __float2bfloat16(0.f);
                rbls[i] = ok ? Bl[(size_t)(k0 + r) * N + n0 + c] : __float2bfloat16(0.f);
            }
        }
    };
    auto stB = [&](int st) {
        if (VEC) {
            int r = tid >> 4, c4 = tid & 15;
            *(uint2*)&Bhs[st][r][c4 * 4] = rbh2;
            *(uint2*)&Bls[st][r][c4 * 4] = rbl2;
        } else {
#pragma unroll
            for (int i = 0; i < 4; i++) {
                int idx = tid + i * 256;
                int r = idx >> 6, c = idx & 63;
                Bhs[st][r][c] = rbhs[i];
                Bls[st][r][c] = rbls[i];
            }
        }
    };

    ldA(0); ldB(0);
    stA(0); stB(0);
    if (bias) {
        for (int i = tid; i < 16 * BN; i += 256)
            Brep[i >> 6][i & 63] = bias[n0 + (i & 63)];
    }
    __syncthreads();

    wmma::fragment<wmma::accumulator, 16, 16, 16, float> cfr[2][2];
#pragma unroll
    for (int mi = 0; mi < 2; mi++)
#pragma unroll
        for (int ni = 0; ni < 2; ni++) {
            if (bias)
                wmma::load_matrix_sync(cfr[mi][ni], &Brep[0][nw + ni * 16], BN, wmma::mem_row_major);
            else
                wmma::fill_fragment(cfr[mi][ni], 0.f);
        }

    const int numK = (K + 15) >> 4;
    int cur = 0;
    for (int t = 0; t < numK; t++) {
        bool hasNext = (t + 1 < numK);
        if (hasNext) { ldA(t + 1); ldB(t + 1); }

        wmma::fragment<wmma::matrix_a, 16, 16, 16, __nv_bfloat16, wmma::row_major> fah[2], fal[2];
#pragma unroll
        for (int mi = 0; mi < 2; mi++) {
            wmma::load_matrix_sync(fah[mi], &Ahs[cur][mw + mi * 16][0], SKA);
            wmma::load_matrix_sync(fal[mi], &Als[cur][mw + mi * 16][0], SKA);
        }
#pragma unroll
        for (int ni = 0; ni < 2; ni++) {
            wmma::fragment<wmma::matrix_b, 16, 16, 16, __nv_bfloat16, wmma::row_major> fbh, fbl;
            wmma::load_matrix_sync(fbh, &Bhs[cur][0][nw + ni * 16], SKB);
            wmma::load_matrix_sync(fbl, &Bls[cur][0][nw + ni * 16], SKB);
#pragma unroll
            for (int mi = 0; mi < 2; mi++) {
                wmma::mma_sync(cfr[mi][ni], fah[mi], fbh, cfr[mi][ni]);
                wmma::mma_sync(cfr[mi][ni], fal[mi], fbh, cfr[mi][ni]);
                wmma::mma_sync(cfr[mi][ni], fah[mi], fbl, cfr[mi][ni]);
            }
        }

        if (hasNext) {
            stA(cur ^ 1); stB(cur ^ 1);
            __syncthreads();
            cur ^= 1;
        }
    }

#pragma unroll
    for (int mi = 0; mi < 2; mi++) {
        int gm = m0 + mw + mi * 16;
#pragma unroll
        for (int ni = 0; ni < 2; ni++) {
            if (relu) {
#pragma unroll
                for (int q = 0; q < cfr[mi][ni].num_elements; q++)
                    cfr[mi][ni].x[q] = fmaxf(cfr[mi][ni].x[q], 0.f);
            }
            wmma::store_matrix_sync(&C[(size_t)gm * N + n0 + nw + ni * 16], cfr[mi][ni], N,
                                    wmma::mem_row_major);
        }
    }
}

// ---------------- GAT output GEMM: Out[:,h*64:+64] = seg0 + seg1 (+bias, relu) ----------------
// A = agg [M,512] (rel0 slice cols 0-255, rel1 slice cols 256-511; head h block at h*64).
// W packed per type: [2 rel][4 h][64 k][64 d], 0.5 pre-folded, bf16 hi/lo.
__launch_bounds__(256, 2)
__global__ void gemm_gat_kernel(const float* __restrict__ A,
                                const __nv_bfloat16* __restrict__ Wh,
                                const __nv_bfloat16* __restrict__ Wl,
                                float* __restrict__ C, const float* __restrict__ bias,
                                int M)
{
    constexpr int BM = 128, SKA = 32, SKB = 80;
    __shared__ __nv_bfloat16 Ahs[2][BM][SKA];
    __shared__ __nv_bfloat16 Als[2][BM][SKA];
    __shared__ __nv_bfloat16 Bhs[2][16][SKB];
    __shared__ __nv_bfloat16 Bls[2][16][SKB];
    __shared__ float Brep[16][64];

    const int tid = threadIdx.x;
    const int wid = tid >> 5;
    const int wm = wid & 3, wn = wid >> 2;
    const int h = blockIdx.x;                 // head 0..3
    const int m0 = blockIdx.y * BM;
    const int mw = wm * 32, nw = wn * 32;

    float4 ra4[2];
    uint2 rbh2, rbl2;

    auto ldA = [&](int t) {
        int colBase = ((t < 4) ? 0 : 256) + h * 64 + (t & 3) * 16;
#pragma unroll
        for (int i = 0; i < 2; i++) {
            int idx = tid + i * 256;
            int r = idx >> 2, c4 = idx & 3;
            int gm = m0 + r;
            ra4[i] = (gm < M) ? *(const float4*)&A[(size_t)gm * 512 + colBase + c4 * 4]
                              : make_float4(0.f, 0.f, 0.f, 0.f);
        }
    };
    auto stA = [&](int st) {
#pragma unroll
        for (int i = 0; i < 2; i++) {
            int idx = tid + i * 256;
            int r = idx >> 2, c4 = idx & 3;
            float v[4] = {ra4[i].x, ra4[i].y, ra4[i].z, ra4[i].w};
#pragma unroll
            for (int j = 0; j < 4; j++) {
                __nv_bfloat16 hh, ll;
                bf16_split(v[j], hh, ll);
                Ahs[st][r][c4 * 4 + j] = hh;
                Als[st][r][c4 * 4 + j] = ll;
            }
        }
    };
    auto ldB = [&](int t) {
        int blk = ((t < 4) ? 0 : 4) + h;
        int rBase = (t & 3) * 16;
        int r = tid >> 4, c4 = tid & 15;
        rbh2 = *(const uint2*)&Wh[blk * 4096 + (rBase + r) * 64 + c4 * 4];
        rbl2 = *(const uint2*)&Wl[blk * 4096 + (rBase + r) * 64 + c4 * 4];
    };
    auto stB = [&](int st) {
        int r = tid >> 4, c4 = tid & 15;
        *(uint2*)&Bhs[st][r][c4 * 4] = rbh2;
        *(uint2*)&Bls[st][r][c4 * 4] = rbl2;
    };

    ldA(0); ldB(0);
    stA(0); stB(0);
    for (int i = tid; i < 16 * 64; i += 256)
        Brep[i >> 6][i & 63] = bias[h * 64 + (i & 63)];
    __syncthreads();

    wmma::fragment<wmma::accumulator, 16, 16, 16, float> cfr[2][2];
#pragma unroll
    for (int mi = 0; mi < 2; mi++)
#pragma unroll
        for (int ni = 0; ni < 2; ni++)
            wmma::load_matrix_sync(cfr[mi][ni], &Brep[0][nw + ni * 16], 64, wmma::mem_row_major);

    int cur = 0;
    for (int t = 0; t < 8; t++) {
        bool hasNext = (t < 7);
        if (hasNext) { ldA(t + 1); ldB(t + 1); }

        wmma::fragment<wmma::matrix_a, 16, 16, 16, __nv_bfloat16, wmma::row_major> fah[2], fal[2];
#pragma unroll
        for (int mi = 0; mi < 2; mi++) {
            wmma::load_matrix_sync(fah[mi], &Ahs[cur][mw + mi * 16][0], SKA);
            wmma::load_matrix_sync(fal[mi], &Als[cur][mw + mi * 16][0], SKA);
        }
#pragma unroll
        for (int ni = 0; ni < 2; ni++) {
            wmma::fragment<wmma::matrix_b, 16, 16, 16, __nv_bfloat16, wmma::row_major> fbh, fbl;
            wmma::load_matrix_sync(fbh, &Bhs[cur][0][nw + ni * 16], SKB);
            wmma::load_matrix_sync(fbl, &Bls[cur][0][nw + ni * 16], SKB);
#pragma unroll
            for (int mi = 0; mi < 2; mi++) {
                wmma::mma_sync(cfr[mi][ni], fah[mi], fbh, cfr[mi][ni]);
                wmma::mma_sync(cfr[mi][ni], fal[mi], fbh, cfr[mi][ni]);
                wmma::mma_sync(cfr[mi][ni], fah[mi], fbl, cfr[mi][ni]);
            }
        }

        if (hasNext) {
            stA(cur ^ 1); stB(cur ^ 1);
            __syncthreads();
            cur ^= 1;
        }
    }

#pragma unroll
    for (int mi = 0; mi < 2; mi++) {
        int gm = m0 + mw + mi * 16;
#pragma unroll
        for (int ni = 0; ni < 2; ni++) {
#pragma unroll
            for (int q = 0; q < cfr[mi][ni].num_elements; q++)
                cfr[mi][ni].x[q] = fmaxf(cfr[mi][ni].x[q], 0.f);
            wmma::store_matrix_sync(&C[(size_t)gm * 256 + h * 64 + nw + ni * 16], cfr[mi][ni], 256,
                                    wmma::mem_row_major);
        }
    }
}

// ---------------- weight split / pack kernels (tiny) ----------------
__global__ void split_plain_kernel(const float* __restrict__ src,
                                   __nv_bfloat16* __restrict__ bh,
                                   __nv_bfloat16* __restrict__ bl, int n)
{
    int i = blockIdx.x * 256 + threadIdx.x;
    if (i >= n) return;
    __nv_bfloat16 h, l;
    bf16_split(src[i], h, l);
    bh[i] = h; bl[i] = l;
}

// gat_W[4][64][256] -> per-type head-blocked [2 typ][2 rel][4 h][64 k][64 d], x0.5.
// Also gbias[typ*256+c] = 0.5*(b[typ][c] + b[typ+2][c]).
__global__ void pack_gatout_kernel(const float* __restrict__ W, const float* __restrict__ gb,
                                   __nv_bfloat16* __restrict__ bh, __nv_bfloat16* __restrict__ bl,
                                   float* __restrict__ gbias)
{
    int idx = blockIdx.x * 256 + threadIdx.x;
    if (idx < 65536) {
        int typ = idx >> 15;
        int rem = idx & 32767;
        int b = rem >> 12;              // rel_idx*4 + h
        int k = (rem >> 6) & 63;
        int d = rem & 63;
        int rel = typ + 2 * (b >> 2);
        int h = b & 3;
        float v = 0.5f * W[(size_t)rel * 16384 + k * 256 + h * 64 + d];
        __nv_bfloat16 hh, ll;
        bf16_split(v, hh, ll);
        bh[idx] = hh; bl[idx] = ll;
    }
    if (idx < 512) {
        int typ = idx >> 8, c = idx & 255;
        gbias[idx] = 0.5f * (gb[typ * 256 + c] + gb[(typ + 2) * 256 + c]);
    }
}

// Wn[4][256][64] -> packed [2][256][128]: type 0 (src=w): rel0|rel2, type 1 (src=t): rel1|rel3
__global__ void pack_wn_kernel(const float* __restrict__ Wn,
                               __nv_bfloat16* __restrict__ bh, __nv_bfloat16* __restrict__ bl)
{
    int idx = blockIdx.x * 256 + threadIdx.x;
    if (idx >= 65536) return;
    int s = idx >> 15;
    int rem = idx & 32767;
    int k = rem >> 7;
    int c = rem & 127;
    int rel = (s ? 1 : 0) + ((c >= 64) ? 2 : 0);
    __nv_bfloat16 h, l;
    bf16_split(Wn[(size_t)rel * 16384 + k * 64 + (c & 63)], h, l);
    bh[idx] = h; bl[idx] = l;
}

// Ws sums -> split [2][256][64]; bias sums fp32
__global__ void wsum_split_kernel(const float* __restrict__ Ws, const float* __restrict__ b,
                                  __nv_bfloat16* __restrict__ bh, __nv_bfloat16* __restrict__ bl,
                                  float* __restrict__ bsum)
{
    int i = blockIdx.x * 256 + threadIdx.x;
    if (i < 32768) {
        int s = i >> 14;
        int j = i & 16383;
        float v = s ? (Ws[16384 + j] + Ws[3 * 16384 + j]) : (Ws[j] + Ws[2 * 16384 + j]);
        __nv_bfloat16 h, l;
        bf16_split(v, h, l);
        bh[i] = h; bl[i] = l;
    }
    if (i < 64) bsum[i] = b[i] + b[2 * 64 + i];
    else if (i < 128) { int j = i - 64; bsum[i] = b[64 + j] + b[3 * 64 + j]; }
}

// ------------- fold attention vectors into K-side: v[k,h] = sum_d W[k, h*64+d]*a[h,d] --------
__global__ void attnvec_kernel(const float* __restrict__ W, const float* __restrict__ al,
                               const float* __restrict__ ar,
                               float* __restrict__ alv, float* __restrict__ arv)
{
    int idx = blockIdx.x * 256 + threadIdx.x;      // 2048 total
    if (idx >= 2048) return;
    int type = idx >> 10;
    int rem = idx & 1023;
    int r = rem >> 8;
    int k = (rem >> 2) & 63;
    int h = rem & 3;
    const float* av = type ? ar : al;
    float s = 0.f;
#pragma unroll 16
    for (int d = 0; d < 64; d++)
        s += W[(size_t)r * 16384 + (size_t)k * 256 + h * 64 + d] * av[r * 256 + h * 64 + d];
    (type ? arv : alv)[r * 256 + k * 4 + h] = s;
}

// ------------- fused el/er projection: one X read computes 4 vec-projections -------------
__global__ void vecproj_fused_kernel(const float* __restrict__ Xt, const float* __restrict__ Xw,
                                     const float* __restrict__ alv, const float* __restrict__ arv,
                                     float* __restrict__ el, float* __restrict__ er,
                                     int NT, int NW)
{
    int type = blockIdx.y;                 // 0 = tx nodes, 1 = w nodes
    const float* X = type ? Xw : Xt;
    int n = type ? NW : NT;
    int e0 = type ? 0 : 1;                 // el relations {e0, e0+2} (this type is src)
    int r0 = type ? 1 : 0;                 // er relations {r0, r0+2} (this type is dst)

    __shared__ float sv[4][256];
    for (int i = threadIdx.x; i < 1024; i += blockDim.x) {
        int v = i >> 8, c = i & 255;
        const float* src = (v < 2) ? (alv + (e0 + 2 * (v & 1)) * 256)
                                   : (arv + (r0 + 2 * (v & 1)) * 256);
        sv[v][c] = src[c];
    }
    __syncthreads();
    int i = blockIdx.x * blockDim.x + threadIdx.x;
    if (i >= n) return;
    const float* x = X + (size_t)i * 64;
    float a[4][4] = {};
#pragma unroll 8
    for (int k = 0; k < 64; k++) {
        float xv = __ldg(&x[k]);
#pragma unroll
        for (int v = 0; v < 4; v++) {
            float4 s4 = *(const float4*)&sv[v][k * 4];
            a[v][0] += xv * s4.x; a[v][1] += xv * s4.y;
            a[v][2] += xv * s4.z; a[v][3] += xv * s4.w;
        }
    }
    *(float4*)&el[(size_t)(e0)     * MAXN * 4 + (size_t)i * 4] = make_float4(a[0][0], a[0][1], a[0][2], a[0][3]);
    *(float4*)&el[(size_t)(e0 + 2) * MAXN * 4 + (size_t)i * 4] = make_float4(a[1][0], a[1][1], a[1][2], a[1][3]);
    *(float4*)&er[(size_t)(r0)     * MAXN * 4 + (size_t)i * 4] = make_float4(a[2][0], a[2][1], a[2][2], a[2][3]);
    *(float4*)&er[(size_t)(r0 + 2) * MAXN * 4 + (size_t)i * 4] = make_float4(a[3][0], a[3][1], a[3][2], a[3][3]);
}

// ---------------- CSR build ----------------
__global__ void hist_kernel(const int* __restrict__ edges, int* __restrict__ cnt, int E, int n)
{
    for (int idx = blockIdx.x * blockDim.x + threadIdx.x; idx < 4 * E; idx += gridDim.x * blockDim.x) {
        int r = idx / E, i = idx - r * E;
        int dst = edges[(size_t)(2 * r + 1) * E + i];
        atomicAdd(&cnt[r * n + dst], 1);
    }
}

__global__ void scan_kernel(const int* __restrict__ cnt, int* __restrict__ rp, int n)
{
    int r = blockIdx.x;
    int t = threadIdx.x;                      // 1024 threads
    int C = (n + 1023) / 1024;
    __shared__ int sums[1024];
    int base = t * C;
    int loc = 0;
    for (int i = 0; i < C; i++) {
        int idx = base + i;
        if (idx < n) loc += cnt[r * n + idx];
    }
    sums[t] = loc;
    __syncthreads();
    for (int off = 1; off < 1024; off <<= 1) {
        int v = (t >= off) ? sums[t - off] : 0;
        __syncthreads();
        sums[t] += v;
        __syncthreads();
    }
    int run = (t == 0) ? 0 : sums[t - 1];
    for (int i = 0; i < C; i++) {
        int idx = base + i;
        if (idx < n) {
            rp[(size_t)r * (n + 1) + idx] = run;
            run += cnt[r * n + idx];
        }
    }
    if (t == 1023) rp[(size_t)r * (n + 1) + n] = sums[1023];
}

__global__ void scatter_kernel(const int* __restrict__ edges, int* __restrict__ cnt,
                               const int* __restrict__ rp, int* __restrict__ col, int E, int n)
{
    for (int idx = blockIdx.x * blockDim.x + threadIdx.x; idx < 4 * E; idx += gridDim.x * blockDim.x) {
        int r = idx / E, i = idx - r * E;
        int src = edges[(size_t)(2 * r) * E + i];
        int dst = edges[(size_t)(2 * r + 1) * E + i];
        int pos = rp[(size_t)r * (n + 1) + dst] + atomicAdd(&cnt[r * n + dst], 1);
        col[(size_t)r * E + pos] = src;
    }
}

// ---------------- GAT aggregation (pre-projection): agg[dst, rel*256+h*64+d] ----------------
// Per edge reads the 64-wide source feature (L2-resident) instead of the 1KB projected row.
__device__ __forceinline__ float lrelu(float x) { return x > 0.f ? x : 0.2f * x; }

__global__ void gat_agg_kernel(float* __restrict__ aggT, float* __restrict__ aggW,
                               const float* __restrict__ Xt, const float* __restrict__ Xw,
                               const float* __restrict__ el, const float* __restrict__ er,
                               const int* __restrict__ rp, const int* __restrict__ col,
                               int NT, int NW, int E)
{
    const size_t EO4 = (size_t)MAXN * 4;
    int yt = blockIdx.y;                 // 0 = tx dst (rel 0,2; src w), 1 = w dst (rel 1,3; src t)
    int n = yt ? NW : NT;
    float* agg = yt ? aggW : aggT;
    const float* X = yt ? Xt : Xw;       // source features
    int ra = yt, rb = yt + 2;

    int w = (blockIdx.x * blockDim.x + threadIdx.x) >> 5;
    int lane = threadIdx.x & 31;
    if (w >= n) return;

    const int h  = lane >> 3;            // head owned by this lane
    const int dq = (lane & 7) * 2;       // float4 index pair into 64-wide x row

    float4 acc[2][2];
#pragma unroll
    for (int q = 0; q < 2; q++) {
        acc[q][0] = make_float4(0.f, 0.f, 0.f, 0.f);
        acc[q][1] = make_float4(0.f, 0.f, 0.f, 0.f);
    }

#pragma unroll
    for (int q = 0; q < 2; q++) {
        int rel = q ? rb : ra;
        const float* elr = el + (size_t)rel * EO4;
        const float* err = er + (size_t)rel * EO4;
        const int* rpr   = rp + (size_t)rel * (MAXN + 1);
        const int* colr  = col + (size_t)rel * E;

        int s0 = rpr[w], s1 = rpr[w + 1];
        if (s1 <= s0) continue;

        float4 e4 = *(const float4*)(err + (size_t)w * 4);
        float er0 = e4.x, er1 = e4.y, er2 = e4.z, er3 = e4.w;

        float m0 = -1e30f, m1 = -1e30f, m2 = -1e30f, m3 = -1e30f;
        for (int e = s0 + lane; e < s1; e += 32) {
            int s = colr[e];
            float4 l4 = *(const float4*)(elr + (size_t)s * 4);
            m0 = fmaxf(m0, lrelu(l4.x + er0));
            m1 = fmaxf(m1, lrelu(l4.y + er1));
            m2 = fmaxf(m2, lrelu(l4.z + er2));
            m3 = fmaxf(m3, lrelu(l4.w + er3));
        }
#pragma unroll
        for (int o = 16; o; o >>= 1) {
            m0 = fmaxf(m0, __shfl_xor_sync(0xffffffffu, m0, o));
            m1 = fmaxf(m1, __shfl_xor_sync(0xffffffffu, m1, o));
            m2 = fmaxf(m2, __shfl_xor_sync(0xffffffffu, m2, o));
            m3 = fmaxf(m3, __shfl_xor_sync(0xffffffffu, m3, o));
        }
        float z0 = 0, z1 = 0, z2 = 0, z3 = 0;
        for (int e = s0 + lane; e < s1; e += 32) {
            int s = colr[e];
            float4 l4 = *(const float4*)(elr + (size_t)s * 4);
            z0 += __expf(lrelu(l4.x + er0) - m0);
            z1 += __expf(lrelu(l4.y + er1) - m1);
            z2 += __expf(lrelu(l4.z + er2) - m2);
            z3 += __expf(lrelu(l4.w + er3) - m3);
        }
#pragma unroll
        for (int o = 16; o; o >>= 1) {
            z0 += __shfl_xor_sync(0xffffffffu, z0, o);
            z1 += __shfl_xor_sync(0xffffffffu, z1, o);
            z2 += __shfl_xor_sync(0xffffffffu, z2, o);
            z3 += __shfl_xor_sync(0xffffffffu, z3, o);
        }
        float i0 = 1.f / z0, i1 = 1.f / z1, i2 = 1.f / z2, i3 = 1.f / z3;

        for (int e = s0; e < s1; e++) {
            int s = colr[e];
            float4 l4 = *(const float4*)(elr + (size_t)s * 4);
            float a0 = __expf(lrelu(l4.x + er0) - m0) * i0;
            float a1 = __expf(lrelu(l4.y + er1) - m1) * i1;
            float a2 = __expf(lrelu(l4.z + er2) - m2) * i2;
            float a3 = __expf(lrelu(l4.w + er3) - m3) * i3;
            float ah = (h < 2) ? ((h == 0) ? a0 : a1) : ((h == 2) ? a2 : a3);
            const float4* xp = (const float4*)(X + (size_t)s * 64);
            float4 x0 = xp[dq];
            float4 x1 = xp[dq + 1];
            acc[q][0].x = fmaf(ah, x0.x, acc[q][0].x);
            acc[q][0].y = fmaf(ah, x0.y, acc[q][0].y);
            acc[q][0].z = fmaf(ah, x0.z, acc[q][0].z);
            acc[q][0].w = fmaf(ah, x0.w, acc[q][0].w);
            acc[q][1].x = fmaf(ah, x1.x, acc[q][1].x);
            acc[q][1].y = fmaf(ah, x1.y, acc[q][1].y);
            acc[q][1].z = fmaf(ah, x1.z, acc[q][1].z);
            acc[q][1].w = fmaf(ah, x1.w, acc[q][1].w);
        }
    }

    float4* op = (float4*)(agg + (size_t)w * 512);
    int base = h * 16 + (lane & 7) * 2;          // float4 index within 256-float slice
    op[base]           = acc[0][0];
    op[base + 1]       = acc[0][1];
    op[64 + base]      = acc[1][0];
    op[64 + base + 1]  = acc[1][1];
}

// ------------- SAGE1 combine: X = relu(X + mean_a(Y[:,0:64]) + mean_b(Y[:,64:128])) ----------
__global__ void sage1_combine_kernel(float* __restrict__ X, const float* __restrict__ Y,
    const int* __restrict__ rpa, const int* __restrict__ cola,
    const int* __restrict__ rpb, const int* __restrict__ colb, int n)
{
    int w = (blockIdx.x * blockDim.x + threadIdx.x) >> 5;
    int lane = threadIdx.x & 31;
    if (w >= n) return;
    float mx = 0.f, my = 0.f;
    {
        int s0 = rpa[w], s1 = rpa[w + 1];
        float sx = 0.f, sy = 0.f;
        for (int e = s0; e < s1; e++) {
            int s = cola[e];
            float2 v = *(const float2*)&Y[(size_t)s * 128 + lane * 2];
            sx += v.x; sy += v.y;
        }
        float inv = 1.f / fmaxf((float)(s1 - s0), 1.f);
        mx += sx * inv; my += sy * inv;
    }
    {
        int s0 = rpb[w], s1 = rpb[w + 1];
        float sx = 0.f, sy = 0.f;
        for (int e = s0; e < s1; e++) {
            int s = colb[e];
            float2 v = *(const float2*)&Y[(size_t)s * 128 + 64 + lane * 2];
            sx += v.x; sy += v.y;
        }
        float inv = 1.f / fmaxf((float)(s1 - s0), 1.f);
        mx += sx * inv; my += sy * inv;
    }
    float2* xp = (float2*)&X[(size_t)w * 64 + lane * 2];
    float2 xv = *xp;
    xv.x = fmaxf(xv.x + mx, 0.f);
    xv.y = fmaxf(xv.y + my, 0.f);
    *xp = xv;
}

// ------------- SAGE2 projections: self (Ws_a+Ws_b) and two y = X@Wn, all dim 2 -------------
__global__ void proj6_kernel(const float* __restrict__ X,
    const float* __restrict__ WsA, const float* __restrict__ WsB,
    const float* __restrict__ WnA, const float* __restrict__ WnB,
    float* __restrict__ selfO, float* __restrict__ yA, float* __restrict__ yB, int n)
{
    __shared__ float sw[3][512];
    for (int i = threadIdx.x; i < 512; i += blockDim.x) {
        sw[0][i] = WsA[i] + WsB[i];
        sw[1][i] = WnA[i];
        sw[2][i] = WnB[i];
    }
    __syncthreads();
    int w = (blockIdx.x * blockDim.x + threadIdx.x) >> 5;
    int lane = threadIdx.x & 31;
    if (w >= n) return;
    float a[6] = {0.f, 0.f, 0.f, 0.f, 0.f, 0.f};
    for (int k = lane; k < 256; k += 32) {
        float x = X[(size_t)w * 256 + k];
        a[0] += x * sw[0][2 * k]; a[1] += x * sw[0][2 * k + 1];
        a[2] += x * sw[1][2 * k]; a[3] += x * sw[1][2 * k + 1];
        a[4] += x * sw[2][2 * k]; a[5] += x * sw[2][2 * k + 1];
    }
#pragma unroll
    for (int o = 16; o; o >>= 1)
#pragma unroll
        for (int j = 0; j < 6; j++)
            a[j] += __shfl_xor_sync(0xffffffffu, a[j], o);
    if (lane == 0) {
        *(float2*)&selfO[(size_t)w * 2] = make_float2(a[0], a[1]);
        *(float2*)&yA[(size_t)w * 2]    = make_float2(a[2], a[3]);
        *(float2*)&yB[(size_t)w * 2]    = make_float2(a[4], a[5]);
    }
}

// ------------- SAGE2 combine: out = self + bA + bB + mean_a(yA) + mean_b(yB) -------------
__global__ void sage2_combine_kernel(float* __restrict__ out,
    const float* __restrict__ selfO, const float* __restrict__ yA, const float* __restrict__ yB,
    const int* __restrict__ rpa, const int* __restrict__ cola,
    const int* __restrict__ rpb, const int* __restrict__ colb,
    const float* __restrict__ bA, const float* __restrict__ bB, int n)
{
    int w = blockIdx.x * blockDim.x + threadIdx.x;
    if (w >= n) return;
    float2 r = *(const float2*)&selfO[(size_t)w * 2];
    r.x += bA[0] + bB[0];
    r.y += bA[1] + bB[1];
    {
        int s0 = rpa[w], s1 = rpa[w + 1];
        float sx = 0.f, sy = 0.f;
        for (int e = s0; e < s1; e++) {
            float2 v = *(const float2*)&yA[(size_t)cola[e] * 2];
            sx += v.x; sy += v.y;
        }
        float inv = 1.f / fmaxf((float)(s1 - s0), 1.f);
        r.x += sx * inv; r.y += sy * inv;
    }
    {
        int s0 = rpb[w], s1 = rpb[w + 1];
        float sx = 0.f, sy = 0.f;
        for (int e = s0; e < s1; e++) {
            float2 v = *(const float2*)&yB[(size_t)colb[e] * 2];
            sx += v.x; sy += v.y;
        }
        float inv = 1.f / fmaxf((float)(s1 - s0), 1.f);
        r.x += sx * inv; r.y += sy * inv;
    }
    *(float2*)&out[(size_t)w * 2] = r;
}

// ---------------- host helpers ----------------
static void gemm_bs(const float* A, const __nv_bfloat16* Bh, const __nv_bfloat16* Bl, float* C,
                    const float* bias, int M, int N, int K, int relu)
{
    dim3 g(N / 64, (M + 127) / 128);
    if ((K & 15) == 0) gemm_bs_kernel<true><<<g, 256>>>(A, Bh, Bl, C, bias, M, N, K, relu);
    else               gemm_bs_kernel<false><<<g, 256>>>(A, Bh, Bl, C, bias, M, N, K, relu);
}

static void gat_layer(const float* gW, const float* gal, const float* gar, const float* gb,
                      const float* Xt, const float* Xw, float* Ot, float* Ow,
                      float* aggT, float* aggW, __nv_bfloat16* bh, __nv_bfloat16* bl,
                      float* gbias, float* el, float* er, float* alv, float* arv,
                      const int* rp, const int* col, int NT, int NW, int E)
{
    attnvec_kernel<<<8, 256>>>(gW, gal, gar, alv, arv);
    pack_gatout_kernel<<<256, 256>>>(gW, gb, bh, bl, gbias);
    int nmax = NT > NW ? NT : NW;
    dim3 gv((nmax + 255) / 256, 2);
    vecproj_fused_kernel<<<gv, 256>>>(Xt, Xw, alv, arv, el, er, NT, NW);
    dim3 ga((nmax + 7) / 8, 2);
    gat_agg_kernel<<<ga, 256>>>(aggT, aggW, Xt, Xw, el, er, rp, col, NT, NW, E);
    gemm_gat_kernel<<<dim3(4, (NT + 127) / 128), 256>>>(aggT, bh, bl, Ot, gbias, NT);
    gemm_gat_kernel<<<dim3(4, (NW + 127) / 128), 256>>>(aggW, bh + 32768, bl + 32768, Ow,
                                                        gbias + 256, NW);
}

extern "C" void kernel_launch(void* const* d_in, const int* in_sizes, int n_in,
                              void* d_out, int out_size)
{
    const float* tx_feat  = (const float*)d_in[0];
    const float* w_feat   = (const float*)d_in[1];
    const int*   edges    = (const int*)d_in[2];
    const float* tx_W     = (const float*)d_in[3];
    const float* tx_b     = (const float*)d_in[4];
    const float* w_W      = (const float*)d_in[5];
    const float* w_b      = (const float*)d_in[6];
    const float* gat1_W   = (const float*)d_in[7];
    const float* gat1_al  = (const float*)d_in[8];
    const float* gat1_ar  = (const float*)d_in[9];
    const float* gat1_b   = (const float*)d_in[10];
    const float* sage1_Ws = (const float*)d_in[11];
    const float* sage1_Wn = (const float*)d_in[12];
    const float* sage1_b  = (const float*)d_in[13];
    const float* gat2_W   = (const float*)d_in[14];
    const float* gat2_al  = (const float*)d_in[15];
    const float* gat2_ar  = (const float*)d_in[16];
    const float* gat2_b   = (const float*)d_in[17];
    const float* sage2_Ws = (const float*)d_in[18];
    const float* sage2_Wn = (const float*)d_in[19];
    const float* sage2_b  = (const float*)d_in[20];

    int NT = in_sizes[0] / 166;
    int NW = in_sizes[1] / 56;
    int E  = in_sizes[2] / 8;
    if (NT > MAXN) NT = MAXN;
    if (NW > MAXN) NW = MAXN;
    if (E > MAXE) E = MAXE;

    float *t0, *w0, *t1, *w1, *hs, *el, *er, *alv, *arv, *bsum, *gbias;
    __nv_bfloat16 *bh, *bl;
    int *cnt, *rp, *col;
    cudaGetSymbolAddress((void**)&t0, d_t0);
    cudaGetSymbolAddress((void**)&w0, d_w0);
    cudaGetSymbolAddress((void**)&t1, d_t1);
    cudaGetSymbolAddress((void**)&w1, d_w1);
    cudaGetSymbolAddress((void**)&hs, d_hs);
    cudaGetSymbolAddress((void**)&el, d_el);
    cudaGetSymbolAddress((void**)&er, d_er);
    cudaGetSymbolAddress((void**)&alv, d_alv);
    cudaGetSymbolAddress((void**)&arv, d_arv);
    cudaGetSymbolAddress((void**)&bh, d_bh16);
    cudaGetSymbolAddress((void**)&bl, d_bl16);
    cudaGetSymbolAddress((void**)&bsum, d_bsum);
    cudaGetSymbolAddress((void**)&gbias, d_gbias);
    cudaGetSymbolAddress((void**)&cnt, d_cnt);
    cudaGetSymbolAddress((void**)&rp, d_rpv);
    cudaGetSymbolAddress((void**)&col, d_colv);

    float* fout = (float*)d_out;
    float* aggT = hs;                                // agg for tx dsts: [MAXN][512]
    float* aggW = hs + (size_t)MAXN * 512;           // agg for w dsts
    float* Yw = hs;                                  // packed Y src=w: [MAXN][128] (reuse)
    float* Yt = hs + (size_t)MAXN * 128;

    const int* rp0 = rp;  const int* rp1 = rp + (MAXN + 1);
    const int* rp2 = rp + 2 * (MAXN + 1);  const int* rp3 = rp + 3 * (MAXN + 1);
    const int* col0 = col; const int* col1 = col + (size_t)E;
    const int* col2 = col + 2 * (size_t)E; const int* col3 = col + 3 * (size_t)E;

    // ---- CSR build (per relation, dst-sorted) ----
    cudaMemsetAsync(cnt, 0, 4 * (size_t)MAXN * sizeof(int));
    hist_kernel<<<(4 * E + 255) / 256, 256>>>(edges, cnt, E, NT);
    scan_kernel<<<4, 1024>>>(cnt, rp, NT);
    cudaMemsetAsync(cnt, 0, 4 * (size_t)MAXN * sizeof(int));
    scatter_kernel<<<(4 * E + 255) / 256, 256>>>(edges, cnt, rp, col, E, NT);

    // ---- S0: input projections (relu) -> width 64 ----
    split_plain_kernel<<<(166 * 64 + 255) / 256, 256>>>(tx_W, bh, bl, 166 * 64);
    gemm_bs(tx_feat, bh, bl, t0, tx_b, NT, 64, 166, 1);
    split_plain_kernel<<<(56 * 64 + 255) / 256, 256>>>(w_W, bh, bl, 56 * 64);
    gemm_bs(w_feat, bh, bl, w0, w_b, NW, 64, 56, 1);

    // ---- S1: hetero GAT1 (64 -> 256): aggregate-then-project ----
    gat_layer(gat1_W, gat1_al, gat1_ar, gat1_b, t0, w0, t1, w1,
              aggT, aggW, bh, bl, gbias, el, er, alv, arv, rp, col, NT, NW, E);

    // ---- S2: hetero SAGE1 (256 -> 64): project-then-aggregate ----
    {
        wsum_split_kernel<<<128, 256>>>(sage1_Ws, sage1_b, bh, bl, bsum);
        gemm_bs(t1, bh,         bl,         t0, bsum,      NT, 64, 256, 0);
        gemm_bs(w1, bh + 16384, bl + 16384, w0, bsum + 64, NW, 64, 256, 0);
        pack_wn_kernel<<<256, 256>>>(sage1_Wn, bh, bl);
        gemm_bs(w1, bh,         bl,         Yw, nullptr, NW, 128, 256, 0);  // src=w: rel0|rel2
        gemm_bs(t1, bh + 32768, bl + 32768, Yt, nullptr, NT, 128, 256, 0);  // src=t: rel1|rel3
        sage1_combine_kernel<<<(NT + 7) / 8, 256>>>(t0, Yw, rp0, col0, rp2, col2, NT);
        sage1_combine_kernel<<<(NW + 7) / 8, 256>>>(w0, Yt, rp1, col1, rp3, col3, NW);
    }

    // ---- S3: hetero GAT2 (64 -> 256): aggregate-then-project ----
    gat_layer(gat2_W, gat2_al, gat2_ar, gat2_b, t0, w0, t1, w1,
              aggT, aggW, bh, bl, gbias, el, er, alv, arv, rp, col, NT, NW, E);

    // ---- S4: hetero SAGE2 (256 -> 2): project-then-aggregate ----
    {
        const size_t Y2 = (size_t)MAXN * 2;
        float* y0 = el + 0 * Y2;  float* y1 = el + 1 * Y2;
        float* y2 = el + 2 * Y2;  float* y3 = el + 3 * Y2;
        float* selfT = er + 0 * Y2;
        float* selfW = er + 1 * Y2;
        proj6_kernel<<<(NT + 7) / 8, 256>>>(t1, sage2_Ws + 0 * 512, sage2_Ws + 2 * 512,
                                            sage2_Wn + 1 * 512, sage2_Wn + 3 * 512,
                                            selfT, y1, y3, NT);
        proj6_kernel<<<(NW + 7) / 8, 256>>>(w1, sage2_Ws + 1 * 512, sage2_Ws + 3 * 512,
                                            sage2_Wn + 0 * 512, sage2_Wn + 2 * 512,
                                            selfW, y0, y2, NW);
        sage2_combine_kernel<<<(NT + 255) / 256, 256>>>(fout, selfT, y0, y2,
            rp0, col0, rp2, col2, sage2_b + 0, sage2_b + 4, NT);
        sage2_combine_kernel<<<(NW + 255) / 256, 256>>>(fout + (size_t)NT * 2, selfW, y1, y3,
            rp1, col1, rp3, col3, sage2_b + 2, sage2_b + 6, NW);
    }
}